// round 1
// baseline (speedup 1.0000x reference)
#include <cuda_runtime.h>
#include <math.h>

// Problem constants
#define NSRC 4000
#define NTGT 4096
#define DIN 128
#define DH 256
#define CATW 896           // 128 + 3*256
#define ALPHA_C 20.0f
#define EPS_C 1e-10f

// ---------------- device scratch (static, no allocation) ----------------
__device__ __align__(128) float g_cat_s[NSRC * CATW];
__device__ __align__(128) float g_cat_t[NTGT * CATW];
__device__ __align__(128) float g_hcat[NTGT * 768];
__device__ __align__(128) float g_feat_s[NSRC * DH];
__device__ __align__(128) float g_feat_t[NTGT * DH];
__device__ __align__(128) float g_Wpack[3 * 768 * DH];
__device__ __align__(128) float g_S0[(size_t)NTGT * NTGT];   // 64MB
__device__ __align__(128) float g_u[NTGT];
__device__ __align__(128) float g_sumA[NTGT];
__device__ __align__(128) float g_sumB[NTGT];
__device__ __align__(128) float g_rcd_s[NSRC];
__device__ __align__(128) float g_rcs_s[NSRC];
__device__ __align__(128) float g_rcd_t[NTGT];
__device__ __align__(128) float g_rcs_t[NTGT];

// ---------------- weight packing: [Wr; W1; W2] per layer ----------------
__global__ void pack_w_kernel(const float* __restrict__ W1_0, const float* __restrict__ W2_0, const float* __restrict__ Wr_0,
                              const float* __restrict__ W1_1, const float* __restrict__ W2_1, const float* __restrict__ Wr_1,
                              const float* __restrict__ W1_2, const float* __restrict__ W2_2, const float* __restrict__ Wr_2,
                              float* __restrict__ Wp)
{
    int gid = blockIdx.x * 256 + threadIdx.x;
    const int L0 = 384 * 256, L1 = 768 * 256;
    if (gid < L0) {
        int r = gid / 256, c = gid - r * 256;
        const float* src = (r < 128) ? Wr_0 : ((r < 256) ? W1_0 : W2_0);
        Wp[gid] = src[(r & 127) * 256 + c];
    } else if (gid < L0 + L1) {
        int g = gid - L0;
        int r = g / 256, c = g - r * 256;
        const float* src = (r < 256) ? Wr_1 : ((r < 512) ? W1_1 : W2_1);
        Wp[768 * 256 + r * 256 + c] = src[(r & 255) * 256 + c];
    } else if (gid < L0 + 2 * L1) {
        int g = gid - L0 - L1;
        int r = g / 256, c = g - r * 256;
        const float* src = (r < 256) ? Wr_2 : ((r < 512) ? W1_2 : W2_2);
        Wp[2 * 768 * 256 + r * 256 + c] = src[(r & 255) * 256 + c];
    }
}

// ---------------- degree counting ----------------
__global__ void counts_zero_kernel()
{
    int i = blockIdx.x * 256 + threadIdx.x;
    if (i < NSRC) { g_rcd_s[i] = 0.f; g_rcs_s[i] = 0.f; }
    if (i < NTGT) { g_rcd_t[i] = 0.f; g_rcs_t[i] = 0.f; }
}
__global__ void count_kernel(const int* __restrict__ esrc, const int* __restrict__ edst, int E,
                             float* __restrict__ cs, float* __restrict__ cd)
{
    int e = blockIdx.x * 256 + threadIdx.x;
    if (e < E) {
        atomicAdd(&cd[edst[e]], 1.0f);
        atomicAdd(&cs[esrc[e]], 1.0f);
    }
}
__global__ void counts_recip_kernel()
{
    int i = blockIdx.x * 256 + threadIdx.x;
    if (i < NSRC) { g_rcd_s[i] = 1.f / fmaxf(g_rcd_s[i], 1.f); g_rcs_s[i] = 1.f / fmaxf(g_rcs_s[i], 1.f); }
    if (i < NTGT) { g_rcd_t[i] = 1.f / fmaxf(g_rcd_t[i], 1.f); g_rcs_t[i] = 1.f / fmaxf(g_rcs_t[i], 1.f); }
}

// ---------------- per-layer prep: hcat = [h | 0 | 0], optional copy of x into cat ----------------
__global__ void prep_kernel(const float* __restrict__ h, int ldh, float* __restrict__ hcat,
                            int fan3, int fan, int n, float* __restrict__ catdst)
{
    int gid = blockIdx.x * 256 + threadIdx.x;
    int per = fan3 >> 2;
    if (gid >= n * per) return;
    int row = gid / per;
    int c4 = (gid - row * per) << 2;
    if (c4 < fan) {
        float4 v = *(const float4*)&h[(size_t)row * ldh + c4];
        *(float4*)&hcat[(size_t)row * fan3 + c4] = v;
        if (catdst) *(float4*)&catdst[(size_t)row * CATW + c4] = v;
    } else {
        *(float4*)&hcat[(size_t)row * fan3 + c4] = make_float4(0.f, 0.f, 0.f, 0.f);
    }
}

// ---------------- edge scatter (mean folded in via reciprocal counts) ----------------
__global__ void scatter_kernel(const float* __restrict__ h, int ldh,
                               const int* __restrict__ esrc, const int* __restrict__ edst,
                               int E, int shift, int fan,
                               const float* __restrict__ rcd, const float* __restrict__ rcs,
                               float* __restrict__ hcat)
{
    int gid = blockIdx.x * 256 + threadIdx.x;
    if (gid >= (E << shift)) return;
    int e = gid >> shift;
    int c4 = (gid & ((1 << shift) - 1)) << 2;
    int s = esrc[e], d = edst[e];
    float4 hs = *(const float4*)&h[(size_t)s * ldh + c4];
    float4 hd = *(const float4*)&h[(size_t)d * ldh + c4];
    float rd = rcd[d], rs = rcs[s];
    float* p1 = &hcat[(size_t)d * 3 * fan + fan + c4];      // agg1: h[src] -> dst
    float* p2 = &hcat[(size_t)s * 3 * fan + 2 * fan + c4];  // agg2: h[dst] -> src
    asm volatile("red.global.add.v4.f32 [%0], {%1,%2,%3,%4};"
                 :: "l"(p1), "f"(hs.x * rd), "f"(hs.y * rd), "f"(hs.z * rd), "f"(hs.w * rd) : "memory");
    asm volatile("red.global.add.v4.f32 [%0], {%1,%2,%3,%4};"
                 :: "l"(p2), "f"(hd.x * rs), "f"(hd.y * rs), "f"(hd.z * rs), "f"(hd.w * rs) : "memory");
}

// ---------------- 64x64 NN GEMM (N fixed 256 via grid, K % 16 == 0), bias + optional relu ----------------
template<int DO_RELU>
__global__ void gemm64_kernel(const float* __restrict__ A, int lda,
                              const float* __restrict__ B,
                              float* __restrict__ C, int ldc,
                              int M, int K,
                              const float* __restrict__ bias)
{
    __shared__ __align__(16) float As[16][64];
    __shared__ __align__(16) float Bs[16][64];
    int tid = threadIdx.x;
    int m0 = blockIdx.y * 64, n0 = blockIdx.x * 64;
    int ar = tid >> 2, ak = (tid & 3) * 4;
    int bk = tid >> 4, bn = (tid & 15) * 4;
    int tx = tid & 15, ty = tid >> 4;
    float acc[4][4] = {};
    for (int k0 = 0; k0 < K; k0 += 16) {
        float4 av = (m0 + ar < M) ? *(const float4*)&A[(size_t)(m0 + ar) * lda + k0 + ak]
                                  : make_float4(0.f, 0.f, 0.f, 0.f);
        As[ak + 0][ar] = av.x; As[ak + 1][ar] = av.y; As[ak + 2][ar] = av.z; As[ak + 3][ar] = av.w;
        *(float4*)&Bs[bk][bn] = *(const float4*)&B[(size_t)(k0 + bk) * 256 + n0 + bn];
        __syncthreads();
#pragma unroll
        for (int k = 0; k < 16; k++) {
            float a[4], b[4];
            *(float4*)a = *(const float4*)&As[k][ty * 4];
            *(float4*)b = *(const float4*)&Bs[k][tx * 4];
#pragma unroll
            for (int i = 0; i < 4; i++)
#pragma unroll
                for (int j = 0; j < 4; j++)
                    acc[i][j] += a[i] * b[j];
        }
        __syncthreads();
    }
#pragma unroll
    for (int i = 0; i < 4; i++) {
        int m = m0 + ty * 4 + i;
        if (m >= M) continue;
        int n = n0 + tx * 4;
        float4 v;
        v.x = acc[i][0] + bias[n + 0];
        v.y = acc[i][1] + bias[n + 1];
        v.z = acc[i][2] + bias[n + 2];
        v.w = acc[i][3] + bias[n + 3];
        if (DO_RELU) {
            v.x = fmaxf(v.x, 0.f); v.y = fmaxf(v.y, 0.f);
            v.z = fmaxf(v.z, 0.f); v.w = fmaxf(v.w, 0.f);
        }
        *(float4*)&C[(size_t)m * ldc + n] = v;
    }
}

// ---------------- row l2 normalize (256 cols) ----------------
__global__ void l2norm_kernel(float* __restrict__ f)
{
    int row = blockIdx.x, t = threadIdx.x;
    float v = f[(size_t)row * 256 + t];
    float s = v * v;
#pragma unroll
    for (int o = 16; o; o >>= 1) s += __shfl_xor_sync(0xffffffffu, s, o);
    __shared__ float sm[8];
    int w = t >> 5;
    if ((t & 31) == 0) sm[w] = s;
    __syncthreads();
    if (t < 8) {
        float tot = sm[t];
#pragma unroll
        for (int o = 4; o; o >>= 1) tot += __shfl_xor_sync(0xffu, tot, o);
        if (t == 0) sm[0] = tot;
    }
    __syncthreads();
    float scale = 1.f / fmaxf(sqrtf(sm[0]), 1e-12f);
    f[(size_t)row * 256 + t] = v * scale;
}

// ---------------- 128x128 NT GEMM (K=256) with exp(alpha*(x+eps)) epilogue into S0 ----------------
__global__ void gemm_nt_exp_kernel(const float* __restrict__ A,
                                   const float* __restrict__ B,
                                   float* __restrict__ C, int M)
{
    __shared__ __align__(16) float As[8][128];
    __shared__ __align__(16) float Bs[8][128];
    int tid = threadIdx.x;
    int m0 = blockIdx.y * 128, n0 = blockIdx.x * 128;
    int lr = tid >> 1, lk = (tid & 1) * 4;
    int tx = tid & 15, ty = tid >> 4;
    float acc[8][8] = {};
    for (int k0 = 0; k0 < 256; k0 += 8) {
        float4 av = (m0 + lr < M) ? *(const float4*)&A[(size_t)(m0 + lr) * 256 + k0 + lk]
                                  : make_float4(0.f, 0.f, 0.f, 0.f);
        As[lk + 0][lr] = av.x; As[lk + 1][lr] = av.y; As[lk + 2][lr] = av.z; As[lk + 3][lr] = av.w;
        float4 bv = *(const float4*)&B[(size_t)(n0 + lr) * 256 + k0 + lk];
        Bs[lk + 0][lr] = bv.x; Bs[lk + 1][lr] = bv.y; Bs[lk + 2][lr] = bv.z; Bs[lk + 3][lr] = bv.w;
        __syncthreads();
#pragma unroll
        for (int k = 0; k < 8; k++) {
            float a[8], b[8];
            *(float4*)(a + 0) = *(const float4*)&As[k][ty * 8];
            *(float4*)(a + 4) = *(const float4*)&As[k][ty * 8 + 4];
            *(float4*)(b + 0) = *(const float4*)&Bs[k][tx * 8];
            *(float4*)(b + 4) = *(const float4*)&Bs[k][tx * 8 + 4];
#pragma unroll
            for (int i = 0; i < 8; i++)
#pragma unroll
                for (int j = 0; j < 8; j++)
                    acc[i][j] += a[i] * b[j];
        }
        __syncthreads();
    }
#pragma unroll
    for (int i = 0; i < 8; i++) {
        int m = m0 + ty * 8 + i;
        if (m >= M) continue;
#pragma unroll
        for (int j = 0; j < 8; j += 4) {
            int n = n0 + tx * 8 + j;
            float4 v;
            v.x = expf(ALPHA_C * (acc[i][j + 0] + EPS_C));
            v.y = expf(ALPHA_C * (acc[i][j + 1] + EPS_C));
            v.z = expf(ALPHA_C * (acc[i][j + 2] + EPS_C));
            v.w = expf(ALPHA_C * (acc[i][j + 3] + EPS_C));
            *(float4*)&C[(size_t)m * NTGT + n] = v;
        }
    }
}

// ---------------- sinkhorn ----------------
__global__ void fill_dummy_kernel(float* __restrict__ S0)
{
    int gid = blockIdx.x * 256 + threadIdx.x;
    if (gid < (NTGT - NSRC) * NTGT)
        S0[(size_t)NSRC * NTGT + gid] = expf(ALPHA_C * (EPS_C + EPS_C));
}

__global__ void sink_init_kernel(float* __restrict__ u, float* __restrict__ sA, float* __restrict__ sB)
{
    int i = blockIdx.x * 256 + threadIdx.x;
    if (i < NTGT) { u[i] = 1.f; sA[i] = 0.f; sB[i] = 0.f; }
}

// colsum_j += sum_i u_i * S0[i][j] over an i-chunk of 128
__global__ void sink_col_kernel(const float* __restrict__ u, float* __restrict__ sum,
                                const float* __restrict__ S0)
{
    int j = blockIdx.x * 256 + threadIdx.x;
    int i0 = blockIdx.y * 128;
    float acc = 0.f;
#pragma unroll 4
    for (int i = i0; i < i0 + 128; i++)
        acc += u[i] * S0[(size_t)i * NTGT + j];
    atomicAdd(&sum[j], acc);
}

// u_i = 1 / sum_j S0[i][j] / colsum_j ; also zero the other colsum buffer
__global__ void sink_row_kernel(float* __restrict__ u, const float* __restrict__ csum,
                                float* __restrict__ zbuf, const float* __restrict__ S0)
{
    int r0 = blockIdx.x * 4;
    int t = threadIdx.x;
    float acc[4] = {0.f, 0.f, 0.f, 0.f};
    for (int j = t * 4; j < NTGT; j += 1024) {
        float4 cs = *(const float4*)&csum[j];
        float4 rv = make_float4(1.f / cs.x, 1.f / cs.y, 1.f / cs.z, 1.f / cs.w);
#pragma unroll
        for (int r = 0; r < 4; r++) {
            float4 s = *(const float4*)&S0[(size_t)(r0 + r) * NTGT + j];
            acc[r] += s.x * rv.x + s.y * rv.y + s.z * rv.z + s.w * rv.w;
        }
    }
#pragma unroll
    for (int r = 0; r < 4; r++)
#pragma unroll
        for (int o = 16; o; o >>= 1) acc[r] += __shfl_xor_sync(0xffffffffu, acc[r], o);
    __shared__ float sm[8][4];
    int w = t >> 5;
    if ((t & 31) == 0) { sm[w][0] = acc[0]; sm[w][1] = acc[1]; sm[w][2] = acc[2]; sm[w][3] = acc[3]; }
    __syncthreads();
    if (t < 4) {
        float s = 0.f;
#pragma unroll
        for (int w2 = 0; w2 < 8; w2++) s += sm[w2][t];
        u[r0 + t] = 1.f / s;
        zbuf[blockIdx.x * 4 + t] = 0.f;
    }
}

// out[i][j] = u_i * S0[i][j] / colsum_j for i < NSRC
__global__ void sink_out_kernel(float* __restrict__ out, const float* __restrict__ u,
                                const float* __restrict__ csum, const float* __restrict__ S0)
{
    int gid = blockIdx.x * 256 + threadIdx.x;
    if (gid >= NSRC * (NTGT / 4)) return;
    int i = gid >> 10;
    int j = (gid & 1023) << 2;
    float ui = u[i];
    float4 cs = *(const float4*)&csum[j];
    float4 s = *(const float4*)&S0[(size_t)i * NTGT + j];
    float4 o = make_float4(ui * s.x / cs.x, ui * s.y / cs.y, ui * s.z / cs.z, ui * s.w / cs.w);
    *(float4*)&out[(size_t)i * NTGT + j] = o;
}

// ---------------- host orchestration ----------------
static void run_graph(const float* x, int n, const int* edges, int E,
                      const float* rcd, const float* rcs,
                      float* cat, float* hcat, float* feat, float* Wp,
                      const float* br0, const float* br1, const float* br2,
                      const float* final_w, const float* final_b)
{
    const int* esrc = edges;
    const int* edst = edges + E;
    const float* brs[3] = {br0, br1, br2};
    for (int l = 0; l < 3; l++) {
        int fan = l ? 256 : 128;
        int fan3 = 3 * fan;
        const float* h = l ? (cat + 128 + (l - 1) * 256) : x;
        int ldh = l ? CATW : 128;
        int tot = n * (fan3 >> 2);
        prep_kernel<<<(tot + 255) / 256, 256>>>(h, ldh, hcat, fan3, fan, n, l == 0 ? cat : nullptr);
        int shift = (fan == 128) ? 5 : 6;
        int st = E << shift;
        scatter_kernel<<<(st + 255) / 256, 256>>>(h, ldh, esrc, edst, E, shift, fan, rcd, rcs, hcat);
        dim3 g(4, (n + 63) / 64);
        gemm64_kernel<1><<<g, 256>>>(hcat, fan3, Wp + l * 768 * 256, cat + 128 + l * 256, CATW,
                                     n, fan3, brs[l]);
    }
    dim3 gf(4, (n + 63) / 64);
    gemm64_kernel<0><<<gf, 256>>>(cat, CATW, final_w, feat, 256, n, CATW, final_b);
    l2norm_kernel<<<n, 256>>>(feat);
}

extern "C" void kernel_launch(void* const* d_in, const int* in_sizes, int n_in,
                              void* d_out, int out_size)
{
    const float* x_s = (const float*)d_in[0];
    const float* x_t = (const float*)d_in[1];
    const int* edges = (const int*)d_in[2];
    const int* edget = (const int*)d_in[3];
    const float* W1_0 = (const float*)d_in[4];
    const float* W2_0 = (const float*)d_in[5];
    const float* Wr_0 = (const float*)d_in[6];
    const float* br_0 = (const float*)d_in[7];
    const float* W1_1 = (const float*)d_in[8];
    const float* W2_1 = (const float*)d_in[9];
    const float* Wr_1 = (const float*)d_in[10];
    const float* br_1 = (const float*)d_in[11];
    const float* W1_2 = (const float*)d_in[12];
    const float* W2_2 = (const float*)d_in[13];
    const float* Wr_2 = (const float*)d_in[14];
    const float* br_2 = (const float*)d_in[15];
    const float* final_w = (const float*)d_in[16];
    const float* final_b = (const float*)d_in[17];
    int ES = in_sizes[2] / 2;
    int ET = in_sizes[3] / 2;

    float *cat_s, *cat_t, *hcat, *feat_s, *feat_t, *Wp, *S0, *u, *sA, *sB;
    float *rcd_s, *rcs_s, *rcd_t, *rcs_t;
    cudaGetSymbolAddress((void**)&cat_s, g_cat_s);
    cudaGetSymbolAddress((void**)&cat_t, g_cat_t);
    cudaGetSymbolAddress((void**)&hcat, g_hcat);
    cudaGetSymbolAddress((void**)&feat_s, g_feat_s);
    cudaGetSymbolAddress((void**)&feat_t, g_feat_t);
    cudaGetSymbolAddress((void**)&Wp, g_Wpack);
    cudaGetSymbolAddress((void**)&S0, g_S0);
    cudaGetSymbolAddress((void**)&u, g_u);
    cudaGetSymbolAddress((void**)&sA, g_sumA);
    cudaGetSymbolAddress((void**)&sB, g_sumB);
    cudaGetSymbolAddress((void**)&rcd_s, g_rcd_s);
    cudaGetSymbolAddress((void**)&rcs_s, g_rcs_s);
    cudaGetSymbolAddress((void**)&rcd_t, g_rcd_t);
    cudaGetSymbolAddress((void**)&rcs_t, g_rcs_t);

    // weights packing + degree reciprocals
    pack_w_kernel<<<1920, 256>>>(W1_0, W2_0, Wr_0, W1_1, W2_1, Wr_1, W1_2, W2_2, Wr_2, Wp);
    counts_zero_kernel<<<(NTGT + 255) / 256, 256>>>();
    count_kernel<<<(ES + 255) / 256, 256>>>(edges, edges + ES, ES, rcs_s, rcd_s);
    count_kernel<<<(ET + 255) / 256, 256>>>(edget, edget + ET, ET, rcs_t, rcd_t);
    counts_recip_kernel<<<(NTGT + 255) / 256, 256>>>();

    // two RelCNN towers
    run_graph(x_s, NSRC, edges, ES, rcd_s, rcs_s, cat_s, hcat, feat_s, Wp, br_0, br_1, br_2, final_w, final_b);
    run_graph(x_t, NTGT, edget, ET, rcd_t, rcs_t, cat_t, hcat, feat_t, Wp, br_0, br_1, br_2, final_w, final_b);

    // match matrix -> exp(alpha*(.+eps)) into S0, dummy rows filled separately
    fill_dummy_kernel<<<((NTGT - NSRC) * NTGT + 255) / 256, 256>>>(S0);
    dim3 gm(NTGT / 128, (NSRC + 127) / 128);
    gemm_nt_exp_kernel<<<gm, 256>>>(feat_s, feat_t, S0, NSRC);

    // sinkhorn: 5 x (col, row) in diagonal-scaling form
    sink_init_kernel<<<(NTGT + 255) / 256, 256>>>(u, sA, sB);
    for (int p = 0; p < 5; p++) {
        float* w = (p & 1) ? sB : sA;
        float* z = (p & 1) ? sA : sB;
        sink_col_kernel<<<dim3(NTGT / 256, NTGT / 128), 256>>>(u, w, S0);
        sink_row_kernel<<<NTGT / 4, 256>>>(u, w, z, S0);
    }
    // last column sums live in sA (p=4 even)
    sink_out_kernel<<<(NSRC * (NTGT / 4) + 255) / 256, 256>>>((float*)d_out, u, sA, S0);
}

// round 4
// speedup vs baseline: 1.3221x; 1.3221x over previous
#include <cuda_runtime.h>
#include <cuda_bf16.h>
#include <math.h>
#include <cstdint>

// Problem constants
#define NSRC 4000
#define NTGT 4096
#define DIN 128
#define DH 256
#define CATW 896           // 128 + 3*256
#define ALPHA_C 20.0f
#define EPS_C 1e-10f

// ================= generic-PTX helpers (sm_80+; NO tcgen05/arch-a) =================
__device__ __forceinline__ uint32_t smem_to_u32(const void* smem_ptr) {
    uint32_t addr;
    asm("{ .reg .u64 tmp; cvta.to.shared.u64 tmp, %1; cvt.u32.u64 %0, tmp; }"
        : "=r"(addr) : "l"(smem_ptr));
    return addr;
}
__device__ __forceinline__ void ldm_x4(uint32_t* r, uint32_t addr) {
    asm volatile("ldmatrix.sync.aligned.m8n8.x4.shared.b16 {%0,%1,%2,%3}, [%4];"
        : "=r"(r[0]), "=r"(r[1]), "=r"(r[2]), "=r"(r[3]) : "r"(addr));
}
__device__ __forceinline__ void mma16816(float* d, const uint32_t* a, const uint32_t* b) {
    asm volatile(
        "mma.sync.aligned.m16n8k16.row.col.f32.bf16.bf16.f32 "
        "{%0,%1,%2,%3}, {%4,%5,%6,%7}, {%8,%9}, {%0,%1,%2,%3};"
        : "+f"(d[0]), "+f"(d[1]), "+f"(d[2]), "+f"(d[3])
        : "r"(a[0]), "r"(a[1]), "r"(a[2]), "r"(a[3]), "r"(b[0]), "r"(b[1]));
}
__device__ __forceinline__ uint32_t pack_bf2(__nv_bfloat16 a, __nv_bfloat16 b) {
    __nv_bfloat162 t = __halves2bfloat162(a, b);
    return *(uint32_t*)&t;
}

// ---------------- device scratch (static, no allocation) ----------------
__device__ __align__(128) float g_cat_s[NSRC * CATW];
__device__ __align__(128) float g_cat_t[NTGT * CATW];
__device__ __align__(128) float g_hcat[NTGT * 768];
__device__ __align__(128) float g_feat_s[NSRC * DH];
__device__ __align__(128) float g_feat_t[NTGT * DH];
__device__ __align__(128) __nv_bfloat16 g_wt_hi[720896];   // [256 x fan3] per layer, K-major
__device__ __align__(128) __nv_bfloat16 g_wt_lo[720896];
__device__ __align__(128) __nv_bfloat16 g_ft_hi[NTGT * DH];
__device__ __align__(128) __nv_bfloat16 g_ft_lo[NTGT * DH];
__device__ __align__(128) float g_S0[(size_t)NTGT * NTGT];   // 64MB
__device__ __align__(128) float g_u[NTGT];
__device__ __align__(128) float g_sumA[NTGT];
__device__ __align__(128) float g_sumB[NTGT];
__device__ __align__(128) float g_rcd_s[NSRC];
__device__ __align__(128) float g_rcs_s[NSRC];
__device__ __align__(128) float g_rcd_t[NTGT];
__device__ __align__(128) float g_rcs_t[NTGT];

// ---------------- weight packing: transposed + split [256 x fan3] ----------------
// element offsets: L0@0 (256x384), L1@98304 (256x768), L2@294912 (256x768), F@491520 (256x896)
__global__ void pack_wt_kernel(const float* __restrict__ W1_0, const float* __restrict__ W2_0, const float* __restrict__ Wr_0,
                               const float* __restrict__ W1_1, const float* __restrict__ W2_1, const float* __restrict__ Wr_1,
                               const float* __restrict__ W1_2, const float* __restrict__ W2_2, const float* __restrict__ Wr_2,
                               const float* __restrict__ final_w,
                               __nv_bfloat16* __restrict__ Whi, __nv_bfloat16* __restrict__ Wlo)
{
    int g = blockIdx.x * 256 + threadIdx.x;
    if (g >= 720896) return;
    float v;
    if (g < 98304) {
        int n = g / 384, k = g - n * 384;
        int sub = k >> 7, kr = k & 127;
        const float* s = (sub == 0) ? Wr_0 : ((sub == 1) ? W1_0 : W2_0);
        v = s[kr * 256 + n];
    } else if (g < 294912) {
        int g2 = g - 98304;
        int n = g2 / 768, k = g2 - n * 768;
        int sub = k >> 8, kr = k & 255;
        const float* s = (sub == 0) ? Wr_1 : ((sub == 1) ? W1_1 : W2_1);
        v = s[kr * 256 + n];
    } else if (g < 491520) {
        int g2 = g - 294912;
        int n = g2 / 768, k = g2 - n * 768;
        int sub = k >> 8, kr = k & 255;
        const float* s = (sub == 0) ? Wr_2 : ((sub == 1) ? W1_2 : W2_2);
        v = s[kr * 256 + n];
    } else {
        int g2 = g - 491520;
        int n = g2 / 896, k = g2 - n * 896;
        v = final_w[k * 256 + n];
    }
    __nv_bfloat16 h = __float2bfloat16(v);
    Whi[g] = h;
    Wlo[g] = __float2bfloat16(v - __bfloat162float(h));
}

// ---------------- degree counting ----------------
__global__ void counts_zero_kernel()
{
    int i = blockIdx.x * 256 + threadIdx.x;
    if (i < NSRC) { g_rcd_s[i] = 0.f; g_rcs_s[i] = 0.f; }
    if (i < NTGT) { g_rcd_t[i] = 0.f; g_rcs_t[i] = 0.f; }
}
__global__ void count_kernel(const int* __restrict__ esrc, const int* __restrict__ edst, int E,
                             float* __restrict__ cs, float* __restrict__ cd)
{
    int e = blockIdx.x * 256 + threadIdx.x;
    if (e < E) {
        atomicAdd(&cd[edst[e]], 1.0f);
        atomicAdd(&cs[esrc[e]], 1.0f);
    }
}
__global__ void counts_recip_kernel()
{
    int i = blockIdx.x * 256 + threadIdx.x;
    if (i < NSRC) { g_rcd_s[i] = 1.f / fmaxf(g_rcd_s[i], 1.f); g_rcs_s[i] = 1.f / fmaxf(g_rcs_s[i], 1.f); }
    if (i < NTGT) { g_rcd_t[i] = 1.f / fmaxf(g_rcd_t[i], 1.f); g_rcs_t[i] = 1.f / fmaxf(g_rcs_t[i], 1.f); }
}

// ---------------- per-layer prep: hcat = [h | 0 | 0], optional copy of x into cat ----------------
__global__ void prep_kernel(const float* __restrict__ h, int ldh, float* __restrict__ hcat,
                            int fan3, int fan, int n, float* __restrict__ catdst)
{
    int gid = blockIdx.x * 256 + threadIdx.x;
    int per = fan3 >> 2;
    if (gid >= n * per) return;
    int row = gid / per;
    int c4 = (gid - row * per) << 2;
    if (c4 < fan) {
        float4 v = *(const float4*)&h[(size_t)row * ldh + c4];
        *(float4*)&hcat[(size_t)row * fan3 + c4] = v;
        if (catdst) *(float4*)&catdst[(size_t)row * CATW + c4] = v;
    } else {
        *(float4*)&hcat[(size_t)row * fan3 + c4] = make_float4(0.f, 0.f, 0.f, 0.f);
    }
}

// ---------------- edge scatter (mean folded in via reciprocal counts) ----------------
__global__ void scatter_kernel(const float* __restrict__ h, int ldh,
                               const int* __restrict__ esrc, const int* __restrict__ edst,
                               int E, int shift, int fan,
                               const float* __restrict__ rcd, const float* __restrict__ rcs,
                               float* __restrict__ hcat)
{
    int gid = blockIdx.x * 256 + threadIdx.x;
    if (gid >= (E << shift)) return;
    int e = gid >> shift;
    int c4 = (gid & ((1 << shift) - 1)) << 2;
    int s = esrc[e], d = edst[e];
    float4 hs = *(const float4*)&h[(size_t)s * ldh + c4];
    float4 hd = *(const float4*)&h[(size_t)d * ldh + c4];
    float rd = rcd[d], rs = rcs[s];
    float* p1 = &hcat[(size_t)d * 3 * fan + fan + c4];      // agg1: h[src] -> dst
    float* p2 = &hcat[(size_t)s * 3 * fan + 2 * fan + c4];  // agg2: h[dst] -> src
    asm volatile("red.global.add.v4.f32 [%0], {%1,%2,%3,%4};"
                 :: "l"(p1), "f"(hs.x * rd), "f"(hs.y * rd), "f"(hs.z * rd), "f"(hs.w * rd) : "memory");
    asm volatile("red.global.add.v4.f32 [%0], {%1,%2,%3,%4};"
                 :: "l"(p2), "f"(hd.x * rs), "f"(hd.y * rs), "f"(hd.z * rs), "f"(hd.w * rs) : "memory");
}

// ================= HMMA bf16-split GEMM (mma.sync m16n8k16, generic PTX) =================
// D[M, gridDim.y*128] = A[M,K] (fp32, split on the fly) x B[N,K]^T (pre-split bf16 hi/lo)
// CTA = 128(M) x 128(N), 8 warps as 4(M) x 2(N); warp = 32x64 = 2x8 m16n8k16 frags.
// 3 passes: Ah*Bh + Ah*Bl + Al*Bh, fp32 accumulate.
// EPI: 0 = bias+relu, 1 = bias, 2 = exp(ALPHA*(x+EPS))
#define PAD 40   // bf16 elements per smem row (80B stride -> conflict-free ldmatrix)

template<int EPI>
__global__ __launch_bounds__(256, 1) void hmma_gemm_kernel(
    const float* __restrict__ A, int lda, int M,
    const __nv_bfloat16* __restrict__ Bhi, const __nv_bfloat16* __restrict__ Blo, int ldb,
    int K,
    const float* __restrict__ bias,
    float* __restrict__ C, size_t ldc)
{
    __shared__ __align__(16) __nv_bfloat16 sAh[128 * PAD], sAl[128 * PAD];
    __shared__ __align__(16) __nv_bfloat16 sBh[128 * PAD], sBl[128 * PAD];
    const int tid = threadIdx.x, wid = tid >> 5, lid = tid & 31;
    const int m0 = blockIdx.x * 128, n0 = blockIdx.y * 128;
    const int wm = (wid >> 1) * 32, wn = (wid & 1) * 64;
    const uint32_t uAh = smem_to_u32(sAh), uAl = smem_to_u32(sAl);
    const uint32_t uBh = smem_to_u32(sBh), uBl = smem_to_u32(sBl);

    float acc[2][8][4] = {};

    for (int k0 = 0; k0 < K; k0 += 32) {
        // ---- A tile [128 x 32] fp32 -> split bf16 hi/lo ----
#pragma unroll
        for (int i = 0; i < 4; i++) {
            int f = tid + i * 256;
            int r = f >> 3, c = (f & 7) << 2;
            float4 v = make_float4(0.f, 0.f, 0.f, 0.f);
            if (m0 + r < M) v = *(const float4*)&A[(size_t)(m0 + r) * lda + k0 + c];
            __nv_bfloat16 h0 = __float2bfloat16(v.x), h1 = __float2bfloat16(v.y);
            __nv_bfloat16 h2 = __float2bfloat16(v.z), h3 = __float2bfloat16(v.w);
            __nv_bfloat16 l0 = __float2bfloat16(v.x - __bfloat162float(h0));
            __nv_bfloat16 l1 = __float2bfloat16(v.y - __bfloat162float(h1));
            __nv_bfloat16 l2 = __float2bfloat16(v.z - __bfloat162float(h2));
            __nv_bfloat16 l3 = __float2bfloat16(v.w - __bfloat162float(h3));
            *(uint2*)&sAh[r * PAD + c] = make_uint2(pack_bf2(h0, h1), pack_bf2(h2, h3));
            *(uint2*)&sAl[r * PAD + c] = make_uint2(pack_bf2(l0, l1), pack_bf2(l2, l3));
        }
        // ---- B tile [128 x 32] bf16 hi/lo (pre-split) ----
#pragma unroll
        for (int i = 0; i < 2; i++) {
            int f = tid + i * 256;
            int r = f >> 2, c = (f & 3) << 3;
            size_t gi = (size_t)(n0 + r) * ldb + k0 + c;
            uint4 vh = *(const uint4*)&Bhi[gi];
            uint4 vl = *(const uint4*)&Blo[gi];
            *(uint2*)&sBh[r * PAD + c]     = make_uint2(vh.x, vh.y);
            *(uint2*)&sBh[r * PAD + c + 4] = make_uint2(vh.z, vh.w);
            *(uint2*)&sBl[r * PAD + c]     = make_uint2(vl.x, vl.y);
            *(uint2*)&sBl[r * PAD + c + 4] = make_uint2(vl.z, vl.w);
        }
        __syncthreads();

#pragma unroll
        for (int kk = 0; kk < 32; kk += 16) {
            uint32_t ah[2][4], al[2][4], bh[4][4], bl[4][4];
#pragma unroll
            for (int mt = 0; mt < 2; mt++) {
                uint32_t row = wm + mt * 16 + (lid & 15);
                uint32_t col = kk + ((lid & 16) >> 1);
                uint32_t off = (row * PAD + col) * 2;
                ldm_x4(ah[mt], uAh + off);
                ldm_x4(al[mt], uAl + off);
            }
#pragma unroll
            for (int p = 0; p < 4; p++) {
                uint32_t row = wn + p * 16 + (lid & 7) + ((lid & 16) >> 1);
                uint32_t col = kk + (lid & 8);
                uint32_t off = (row * PAD + col) * 2;
                ldm_x4(bh[p], uBh + off);
                ldm_x4(bl[p], uBl + off);
            }
#pragma unroll
            for (int mt = 0; mt < 2; mt++)
#pragma unroll
                for (int nt = 0; nt < 8; nt++) {
                    const uint32_t* bhp = &bh[nt >> 1][(nt & 1) << 1];
                    const uint32_t* blp = &bl[nt >> 1][(nt & 1) << 1];
                    mma16816(acc[mt][nt], ah[mt], bhp);
                    mma16816(acc[mt][nt], ah[mt], blp);
                    mma16816(acc[mt][nt], al[mt], bhp);
                }
        }
        __syncthreads();
    }

    // ---- epilogue ----
    const int g = lid >> 2, t2 = (lid & 3) << 1;
#pragma unroll
    for (int mt = 0; mt < 2; mt++) {
        int r0 = m0 + wm + mt * 16 + g;
#pragma unroll
        for (int nt = 0; nt < 8; nt++) {
            int col = n0 + wn + nt * 8 + t2;
            float* a = acc[mt][nt];
            float b0 = 0.f, b1 = 0.f;
            if (EPI < 2) { b0 = __ldg(&bias[col]); b1 = __ldg(&bias[col + 1]); }
#pragma unroll
            for (int hrow = 0; hrow < 2; hrow++) {
                int row = r0 + hrow * 8;
                if (row >= M) continue;
                float2 v;
                v.x = a[hrow * 2 + 0];
                v.y = a[hrow * 2 + 1];
                if (EPI == 2) {
                    v.x = expf(ALPHA_C * (v.x + EPS_C));
                    v.y = expf(ALPHA_C * (v.y + EPS_C));
                } else {
                    v.x += b0; v.y += b1;
                    if (EPI == 0) { v.x = fmaxf(v.x, 0.f); v.y = fmaxf(v.y, 0.f); }
                }
                *(float2*)&C[(size_t)row * ldc + col] = v;
            }
        }
    }
}

// ---------------- row l2 normalize (256 cols) ----------------
__global__ void l2norm_kernel(float* __restrict__ f)
{
    int row = blockIdx.x, t = threadIdx.x;
    float v = f[(size_t)row * 256 + t];
    float s = v * v;
#pragma unroll
    for (int o = 16; o; o >>= 1) s += __shfl_xor_sync(0xffffffffu, s, o);
    __shared__ float sm[8];
    int w = t >> 5;
    if ((t & 31) == 0) sm[w] = s;
    __syncthreads();
    if (t < 8) {
        float tot = sm[t];
#pragma unroll
        for (int o = 4; o; o >>= 1) tot += __shfl_xor_sync(0xffu, tot, o);
        if (t == 0) sm[0] = tot;
    }
    __syncthreads();
    float scale = 1.f / fmaxf(sqrtf(sm[0]), 1e-12f);
    f[(size_t)row * 256 + t] = v * scale;
}

// ---------------- split feat -> bf16 hi/lo ----------------
__global__ void split_kernel(const float* __restrict__ f,
                             __nv_bfloat16* __restrict__ hi, __nv_bfloat16* __restrict__ lo, int n)
{
    int g = blockIdx.x * 256 + threadIdx.x;
    if (g >= n) return;
    float v = f[g];
    __nv_bfloat16 h = __float2bfloat16(v);
    hi[g] = h;
    lo[g] = __float2bfloat16(v - __bfloat162float(h));
}

// ---------------- sinkhorn ----------------
__global__ void fill_dummy_kernel(float* __restrict__ S0)
{
    int gid = blockIdx.x * 256 + threadIdx.x;
    if (gid < (NTGT - NSRC) * NTGT)
        S0[(size_t)NSRC * NTGT + gid] = expf(ALPHA_C * (EPS_C + EPS_C));
}

__global__ void sink_init_kernel(float* __restrict__ u, float* __restrict__ sA, float* __restrict__ sB)
{
    int i = blockIdx.x * 256 + threadIdx.x;
    if (i < NTGT) { u[i] = 1.f; sA[i] = 0.f; sB[i] = 0.f; }
}

__global__ void sink_col_kernel(const float* __restrict__ u, float* __restrict__ sum,
                                const float* __restrict__ S0)
{
    int j = blockIdx.x * 256 + threadIdx.x;
    int i0 = blockIdx.y * 128;
    float acc = 0.f;
#pragma unroll 4
    for (int i = i0; i < i0 + 128; i++)
        acc += u[i] * S0[(size_t)i * NTGT + j];
    atomicAdd(&sum[j], acc);
}

__global__ void sink_row_kernel(float* __restrict__ u, const float* __restrict__ csum,
                                float* __restrict__ zbuf, const float* __restrict__ S0)
{
    int r0 = blockIdx.x * 4;
    int t = threadIdx.x;
    float acc[4] = {0.f, 0.f, 0.f, 0.f};
    for (int j = t * 4; j < NTGT; j += 1024) {
        float4 cs = *(const float4*)&csum[j];
        float4 rv = make_float4(1.f / cs.x, 1.f / cs.y, 1.f / cs.z, 1.f / cs.w);
#pragma unroll
        for (int r = 0; r < 4; r++) {
            float4 s = *(const float4*)&S0[(size_t)(r0 + r) * NTGT + j];
            acc[r] += s.x * rv.x + s.y * rv.y + s.z * rv.z + s.w * rv.w;
        }
    }
#pragma unroll
    for (int r = 0; r < 4; r++)
#pragma unroll
        for (int o = 16; o; o >>= 1) acc[r] += __shfl_xor_sync(0xffffffffu, acc[r], o);
    __shared__ float sm[8][4];
    int w = t >> 5;
    if ((t & 31) == 0) { sm[w][0] = acc[0]; sm[w][1] = acc[1]; sm[w][2] = acc[2]; sm[w][3] = acc[3]; }
    __syncthreads();
    if (t < 4) {
        float s = 0.f;
#pragma unroll
        for (int w2 = 0; w2 < 8; w2++) s += sm[w2][t];
        u[r0 + t] = 1.f / s;
        zbuf[blockIdx.x * 4 + t] = 0.f;
    }
}

__global__ void sink_out_kernel(float* __restrict__ out, const float* __restrict__ u,
                                const float* __restrict__ csum, const float* __restrict__ S0)
{
    int gid = blockIdx.x * 256 + threadIdx.x;
    if (gid >= NSRC * (NTGT / 4)) return;
    int i = gid >> 10;
    int j = (gid & 1023) << 2;
    float ui = u[i];
    float4 cs = *(const float4*)&csum[j];
    float4 s = *(const float4*)&S0[(size_t)i * NTGT + j];
    float4 o = make_float4(ui * s.x / cs.x, ui * s.y / cs.y, ui * s.z / cs.z, ui * s.w / cs.w);
    *(float4*)&out[(size_t)i * NTGT + j] = o;
}

// ---------------- host orchestration ----------------
static void run_graph(const float* x, int n, const int* edges, int E,
                      const float* rcd, const float* rcs,
                      float* cat, float* hcat, float* feat,
                      const __nv_bfloat16* Whi, const __nv_bfloat16* Wlo,
                      const float* br0, const float* br1, const float* br2,
                      const float* final_b)
{
    const int* esrc = edges;
    const int* edst = edges + E;
    const float* brs[3] = {br0, br1, br2};
    const int woff[3] = {0, 98304, 294912};
    int mtiles = (n + 127) / 128;
    for (int l = 0; l < 3; l++) {
        int fan = l ? 256 : 128;
        int fan3 = 3 * fan;
        const float* h = l ? (cat + 128 + (l - 1) * 256) : x;
        int ldh = l ? CATW : 128;
        int tot = n * (fan3 >> 2);
        prep_kernel<<<(tot + 255) / 256, 256>>>(h, ldh, hcat, fan3, fan, n, l == 0 ? cat : nullptr);
        int shift = (fan == 128) ? 5 : 6;
        int st = E << shift;
        scatter_kernel<<<(st + 255) / 256, 256>>>(h, ldh, esrc, edst, E, shift, fan, rcd, rcs, hcat);
        hmma_gemm_kernel<0><<<dim3(mtiles, 2), 256>>>(
            hcat, fan3, n, Whi + woff[l], Wlo + woff[l], fan3, fan3, brs[l],
            cat + 128 + l * 256, (size_t)CATW);
    }
    hmma_gemm_kernel<1><<<dim3(mtiles, 2), 256>>>(
        cat, CATW, n, Whi + 491520, Wlo + 491520, 896, 896, final_b, feat, (size_t)256);
    l2norm_kernel<<<n, 256>>>(feat);
}

extern "C" void kernel_launch(void* const* d_in, const int* in_sizes, int n_in,
                              void* d_out, int out_size)
{
    const float* x_s = (const float*)d_in[0];
    const float* x_t = (const float*)d_in[1];
    const int* edges = (const int*)d_in[2];
    const int* edget = (const int*)d_in[3];
    const float* W1_0 = (const float*)d_in[4];
    const float* W2_0 = (const float*)d_in[5];
    const float* Wr_0 = (const float*)d_in[6];
    const float* br_0 = (const float*)d_in[7];
    const float* W1_1 = (const float*)d_in[8];
    const float* W2_1 = (const float*)d_in[9];
    const float* Wr_1 = (const float*)d_in[10];
    const float* br_1 = (const float*)d_in[11];
    const float* W1_2 = (const float*)d_in[12];
    const float* W2_2 = (const float*)d_in[13];
    const float* Wr_2 = (const float*)d_in[14];
    const float* br_2 = (const float*)d_in[15];
    const float* final_w = (const float*)d_in[16];
    const float* final_b = (const float*)d_in[17];
    int ES = in_sizes[2] / 2;
    int ET = in_sizes[3] / 2;

    float *cat_s, *cat_t, *hcat, *feat_s, *feat_t, *S0, *u, *sA, *sB;
    float *rcd_s, *rcs_s, *rcd_t, *rcs_t;
    __nv_bfloat16 *wt_hi, *wt_lo, *ft_hi, *ft_lo;
    cudaGetSymbolAddress((void**)&cat_s, g_cat_s);
    cudaGetSymbolAddress((void**)&cat_t, g_cat_t);
    cudaGetSymbolAddress((void**)&hcat, g_hcat);
    cudaGetSymbolAddress((void**)&feat_s, g_feat_s);
    cudaGetSymbolAddress((void**)&feat_t, g_feat_t);
    cudaGetSymbolAddress((void**)&wt_hi, g_wt_hi);
    cudaGetSymbolAddress((void**)&wt_lo, g_wt_lo);
    cudaGetSymbolAddress((void**)&ft_hi, g_ft_hi);
    cudaGetSymbolAddress((void**)&ft_lo, g_ft_lo);
    cudaGetSymbolAddress((void**)&S0, g_S0);
    cudaGetSymbolAddress((void**)&u, g_u);
    cudaGetSymbolAddress((void**)&sA, g_sumA);
    cudaGetSymbolAddress((void**)&sB, g_sumB);
    cudaGetSymbolAddress((void**)&rcd_s, g_rcd_s);
    cudaGetSymbolAddress((void**)&rcs_s, g_rcs_s);
    cudaGetSymbolAddress((void**)&rcd_t, g_rcd_t);
    cudaGetSymbolAddress((void**)&rcs_t, g_rcs_t);

    // weights packing (transpose + bf16 split) + degree reciprocals
    pack_wt_kernel<<<(720896 + 255) / 256, 256>>>(W1_0, W2_0, Wr_0, W1_1, W2_1, Wr_1,
                                                  W1_2, W2_2, Wr_2, final_w, wt_hi, wt_lo);
    counts_zero_kernel<<<(NTGT + 255) / 256, 256>>>();
    count_kernel<<<(ES + 255) / 256, 256>>>(edges, edges + ES, ES, rcs_s, rcd_s);
    count_kernel<<<(ET + 255) / 256, 256>>>(edget, edget + ET, ET, rcs_t, rcd_t);
    counts_recip_kernel<<<(NTGT + 255) / 256, 256>>>();

    // two RelCNN towers
    run_graph(x_s, NSRC, edges, ES, rcd_s, rcs_s, cat_s, hcat, feat_s, wt_hi, wt_lo, br_0, br_1, br_2, final_b);
    run_graph(x_t, NTGT, edget, ET, rcd_t, rcs_t, cat_t, hcat, feat_t, wt_hi, wt_lo, br_0, br_1, br_2, final_b);

    // split normalized target feats for MMA B operand
    split_kernel<<<(NTGT * DH + 255) / 256, 256>>>(feat_t, ft_hi, ft_lo, NTGT * DH);

    // match matrix -> exp(alpha*(.+eps)) into S0, dummy rows filled separately
    fill_dummy_kernel<<<((NTGT - NSRC) * NTGT + 255) / 256, 256>>>(S0);
    hmma_gemm_kernel<2><<<dim3((NSRC + 127) / 128, NTGT / 128), 256>>>(
        feat_s, 256, NSRC, ft_hi, ft_lo, 256, 256, nullptr, S0, (size_t)NTGT);

    // sinkhorn: 5 x (col, row) in diagonal-scaling form
    sink_init_kernel<<<(NTGT + 255) / 256, 256>>>(u, sA, sB);
    for (int p = 0; p < 5; p++) {
        float* w = (p & 1) ? sB : sA;
        float* z = (p & 1) ? sA : sB;
        sink_col_kernel<<<dim3(NTGT / 256, NTGT / 128), 256>>>(u, w, S0);
        sink_row_kernel<<<NTGT / 4, 256>>>(u, w, z, S0);
    }
    sink_out_kernel<<<(NSRC * (NTGT / 4) + 255) / 256, 256>>>((float*)d_out, u, sA, S0);
}

// round 12
// speedup vs baseline: 1.6932x; 1.2807x over previous
#include <cuda_runtime.h>
#include <cuda_bf16.h>
#include <math.h>
#include <cstdint>

// Problem constants
#define NSRC 4000
#define NTGT 4096
#define TOFF 4096            // target tower row offset in merged node space
#define NROW 8192            // merged rows (4096 + 4096)
#define DIN 128
#define DH 256
#define CATW 896             // 128 + 3*256
#define ALPHA_C 20.0f
#define EPS_C 1e-10f

// ================= generic-PTX helpers (sm_80+; NO tcgen05/arch-a) =================
__device__ __forceinline__ uint32_t smem_to_u32(const void* smem_ptr) {
    uint32_t addr;
    asm("{ .reg .u64 tmp; cvta.to.shared.u64 tmp, %1; cvt.u32.u64 %0, tmp; }"
        : "=r"(addr) : "l"(smem_ptr));
    return addr;
}
__device__ __forceinline__ void ldm_x4(uint32_t* r, uint32_t addr) {
    asm volatile("ldmatrix.sync.aligned.m8n8.x4.shared.b16 {%0,%1,%2,%3}, [%4];"
        : "=r"(r[0]), "=r"(r[1]), "=r"(r[2]), "=r"(r[3]) : "r"(addr));
}
__device__ __forceinline__ void mma16816(float* d, const uint32_t* a, const uint32_t* b) {
    asm volatile(
        "mma.sync.aligned.m16n8k16.row.col.f32.bf16.bf16.f32 "
        "{%0,%1,%2,%3}, {%4,%5,%6,%7}, {%8,%9}, {%0,%1,%2,%3};"
        : "+f"(d[0]), "+f"(d[1]), "+f"(d[2]), "+f"(d[3])
        : "r"(a[0]), "r"(a[1]), "r"(a[2]), "r"(a[3]), "r"(b[0]), "r"(b[1]));
}
__device__ __forceinline__ void cpa16(uint32_t saddr, const void* g) {
    asm volatile("cp.async.cg.shared.global [%0], [%1], 16;" :: "r"(saddr), "l"(g));
}
#define CP_COMMIT() asm volatile("cp.async.commit_group;" ::: "memory")
#define CP_WAIT1()  asm volatile("cp.async.wait_group 1;" ::: "memory")
#define CP_WAIT0()  asm volatile("cp.async.wait_group 0;" ::: "memory")
__device__ __forceinline__ uint32_t pack_bf2(__nv_bfloat16 a, __nv_bfloat16 b) {
    __nv_bfloat162 t = __halves2bfloat162(a, b);
    return *(uint32_t*)&t;
}
__device__ __forceinline__ void split1(float v, __nv_bfloat16& h, __nv_bfloat16& l) {
    h = __float2bfloat16(v);
    l = __float2bfloat16(v - __bfloat162float(h));
}

// ---------------- device scratch (static, no allocation) ----------------
__device__ __align__(128) float g_cat[(size_t)NROW * CATW];                 // fp32 concat features
__device__ __align__(128) __nv_bfloat16 g_cat_hi[(size_t)NROW * CATW];
__device__ __align__(128) __nv_bfloat16 g_cat_lo[(size_t)NROW * CATW];
__device__ __align__(128) float g_hcat[(size_t)NROW * 768];
__device__ __align__(128) __nv_bfloat16 g_hc_hi[(size_t)NROW * 768];
__device__ __align__(128) __nv_bfloat16 g_hc_lo[(size_t)NROW * 768];
__device__ __align__(128) float g_feat[(size_t)NROW * DH];
__device__ __align__(128) __nv_bfloat16 g_ft_hi[(size_t)NROW * DH];
__device__ __align__(128) __nv_bfloat16 g_ft_lo[(size_t)NROW * DH];
__device__ __align__(128) __nv_bfloat16 g_wt_hi[720896];                    // [256 x fan3] K-major
__device__ __align__(128) __nv_bfloat16 g_wt_lo[720896];
__device__ __align__(128) float g_S0[(size_t)NTGT * NTGT];                  // 64MB
__device__ __align__(128) float g_cs[5 * NTGT];                             // colsum buffers
__device__ __align__(128) float g_rcd[NROW];
__device__ __align__(128) float g_rcs[NROW];

// ---------------- weight packing: transposed + split [256 x fan3] ----------------
__global__ void pack_wt_kernel(const float* __restrict__ W1_0, const float* __restrict__ W2_0, const float* __restrict__ Wr_0,
                               const float* __restrict__ W1_1, const float* __restrict__ W2_1, const float* __restrict__ Wr_1,
                               const float* __restrict__ W1_2, const float* __restrict__ W2_2, const float* __restrict__ Wr_2,
                               const float* __restrict__ final_w)
{
    int g = blockIdx.x * 256 + threadIdx.x;
    if (g >= 720896) return;
    float v;
    if (g < 98304) {
        int n = g / 384, k = g - n * 384;
        int sub = k >> 7, kr = k & 127;
        const float* s = (sub == 0) ? Wr_0 : ((sub == 1) ? W1_0 : W2_0);
        v = s[kr * 256 + n];
    } else if (g < 294912) {
        int g2 = g - 98304;
        int n = g2 / 768, k = g2 - n * 768;
        int sub = k >> 8, kr = k & 255;
        const float* s = (sub == 0) ? Wr_1 : ((sub == 1) ? W1_1 : W2_1);
        v = s[kr * 256 + n];
    } else if (g < 491520) {
        int g2 = g - 294912;
        int n = g2 / 768, k = g2 - n * 768;
        int sub = k >> 8, kr = k & 255;
        const float* s = (sub == 0) ? Wr_2 : ((sub == 1) ? W1_2 : W2_2);
        v = s[kr * 256 + n];
    } else {
        int g2 = g - 491520;
        int n = g2 / 896, k = g2 - n * 896;
        v = final_w[k * 256 + n];
    }
    __nv_bfloat16 h, l; split1(v, h, l);
    g_wt_hi[g] = h; g_wt_lo[g] = l;
}

// ---------------- init: zero degree arrays + colsum buffers ----------------
__global__ void init_kernel()
{
    int i = blockIdx.x * 256 + threadIdx.x;
    if (i < NROW) { g_rcd[i] = 0.f; g_rcs[i] = 0.f; }
    if (i < NTGT) {
#pragma unroll
        for (int b = 0; b < 5; b++) g_cs[b * NTGT + i] = 0.f;
    }
}
__global__ void count_kernel(const int* __restrict__ esrc, const int* __restrict__ edst, int E, int base)
{
    int e = blockIdx.x * 256 + threadIdx.x;
    if (e < E) {
        atomicAdd(&g_rcd[base + edst[e]], 1.0f);
        atomicAdd(&g_rcs[base + esrc[e]], 1.0f);
    }
}
__global__ void recip_kernel()
{
    int i = blockIdx.x * 256 + threadIdx.x;
    if (i < NROW) {
        g_rcd[i] = 1.f / fmaxf(g_rcd[i], 1.f);
        g_rcs[i] = 1.f / fmaxf(g_rcs[i], 1.f);
    }
}

// ---------------- layer 0 prep: hcat=[x|0|0], cat[:, :128]=x (+ split) ----------------
__global__ void prep0_kernel(const float* __restrict__ xs, const float* __restrict__ xt)
{
    int gid = blockIdx.x * 256 + threadIdx.x;       // NROW * 96 threads
    if (gid >= NROW * 96) return;
    int row = gid / 96, c4 = (gid - row * 96) * 4;
    if (c4 < 128) {
        float4 v = make_float4(0.f, 0.f, 0.f, 0.f);
        if (row < NSRC) v = *(const float4*)&xs[(size_t)row * 128 + c4];
        else if (row >= TOFF) v = *(const float4*)&xt[(size_t)(row - TOFF) * 128 + c4];
        *(float4*)&g_hcat[(size_t)row * 384 + c4] = v;
        *(float4*)&g_cat[(size_t)row * CATW + c4] = v;
        __nv_bfloat16 h0, l0, h1, l1, h2, l2, h3, l3;
        split1(v.x, h0, l0); split1(v.y, h1, l1); split1(v.z, h2, l2); split1(v.w, h3, l3);
        size_t o = (size_t)row * CATW + c4;
        *(uint2*)&g_cat_hi[o] = make_uint2(pack_bf2(h0, h1), pack_bf2(h2, h3));
        *(uint2*)&g_cat_lo[o] = make_uint2(pack_bf2(l0, l1), pack_bf2(l2, l3));
    } else {
        *(float4*)&g_hcat[(size_t)row * 384 + c4] = make_float4(0.f, 0.f, 0.f, 0.f);
    }
}

// ---------------- layers 1-2 prep: hcat=[h|0|0], h = cat column block ----------------
__global__ void prep12_kernel(const float* __restrict__ h)
{
    int gid = blockIdx.x * 256 + threadIdx.x;       // NROW * 192 threads
    if (gid >= NROW * 192) return;
    int row = gid / 192, c4 = (gid - row * 192) * 4;
    float4 v = make_float4(0.f, 0.f, 0.f, 0.f);
    if (c4 < 256) v = *(const float4*)&h[(size_t)row * CATW + c4];
    *(float4*)&g_hcat[(size_t)row * 768 + c4] = v;
}

// ---------------- merged edge scatter ----------------
__global__ void scatter_kernel(const int* __restrict__ es_s, const int* __restrict__ ed_s, int Es,
                               const int* __restrict__ es_t, const int* __restrict__ ed_t, int Et,
                               int shift, int fan)
{
    int gid = blockIdx.x * 256 + threadIdx.x;
    if (gid >= ((Es + Et) << shift)) return;
    int e = gid >> shift;
    int c4 = (gid & ((1 << shift) - 1)) << 2;
    int s, d;
    if (e < Es) { s = es_s[e]; d = ed_s[e]; }
    else { int e2 = e - Es; s = es_t[e2] + TOFF; d = ed_t[e2] + TOFF; }
    int fan3 = 3 * fan;
    float4 hs = *(const float4*)&g_hcat[(size_t)s * fan3 + c4];
    float4 hd = *(const float4*)&g_hcat[(size_t)d * fan3 + c4];
    float rd = g_rcd[d], rs = g_rcs[s];
    float* p1 = &g_hcat[(size_t)d * fan3 + fan + c4];
    float* p2 = &g_hcat[(size_t)s * fan3 + 2 * fan + c4];
    asm volatile("red.global.add.v4.f32 [%0], {%1,%2,%3,%4};"
                 :: "l"(p1), "f"(hs.x * rd), "f"(hs.y * rd), "f"(hs.z * rd), "f"(hs.w * rd) : "memory");
    asm volatile("red.global.add.v4.f32 [%0], {%1,%2,%3,%4};"
                 :: "l"(p2), "f"(hd.x * rs), "f"(hd.y * rs), "f"(hd.z * rs), "f"(hd.w * rs) : "memory");
}

// ---------------- split hcat fp32 -> bf16 hi/lo ----------------
__global__ void split_hcat_kernel(int n4)   // n4 = NROW*fan3/4
{
    int g = blockIdx.x * 256 + threadIdx.x;
    if (g >= n4) return;
    size_t o = (size_t)g * 4;
    float4 v = *(const float4*)&g_hcat[o];
    __nv_bfloat16 h0, l0, h1, l1, h2, l2, h3, l3;
    split1(v.x, h0, l0); split1(v.y, h1, l1); split1(v.z, h2, l2); split1(v.w, h3, l3);
    *(uint2*)&g_hc_hi[o] = make_uint2(pack_bf2(h0, h1), pack_bf2(h2, h3));
    *(uint2*)&g_hc_lo[o] = make_uint2(pack_bf2(l0, l1), pack_bf2(l2, l3));
}

// ================= HMMA bf16-split GEMM, cp.async 2-stage =================
// CTA = 128x128, 8 warps 4x2, warp 32x64. 3 passes Ah*Bh + Ah*Bl + Al*Bh.
// EPI: 0 = bias+relu, write C fp32 + Chi/Clo bf16 ; 1 = bias, C fp32 ; 2 = exp + colsum into cs0
#define PAD 40                      // bf16/row in smem (80B stride, conflict-free ldmatrix)
#define TILE_B 10240                // 128*PAD*2 bytes
#define SMEM_GEMM (2*4*TILE_B + 512)

template<int EPI>
__global__ __launch_bounds__(256, 1) void gemm_kernel(
    const __nv_bfloat16* __restrict__ Ahi, const __nv_bfloat16* __restrict__ Alo, int lda,
    const __nv_bfloat16* __restrict__ Bhi, const __nv_bfloat16* __restrict__ Blo, int ldb,
    int K, const float* __restrict__ bias,
    float* __restrict__ C, __nv_bfloat16* __restrict__ Chi, __nv_bfloat16* __restrict__ Clo,
    int ldc, float* __restrict__ cs0)
{
    extern __shared__ char smem[];
    const uint32_t sb = smem_to_u32(smem);
    const int tid = threadIdx.x, wid = tid >> 5, lid = tid & 31;
    const int m0 = blockIdx.x * 128, n0 = blockIdx.y * 128;
    const int wm = (wid >> 1) * 32, wn = (wid & 1) * 64;

    const int nk = K >> 5;
    float acc[2][8][4] = {};

    // prefetch stage 0
    {
#pragma unroll
        for (int i = 0; i < 2; i++) {
            int q = tid + i * 256;
            int r = q >> 2, cc = (q & 3) << 3;
            uint32_t so = r * 80 + cc * 2;
            size_t ga = (size_t)(m0 + r) * lda + cc;
            size_t gb = (size_t)(n0 + r) * ldb + cc;
            cpa16(sb + 0 * TILE_B + so, Ahi + ga);
            cpa16(sb + 1 * TILE_B + so, Alo + ga);
            cpa16(sb + 2 * TILE_B + so, Bhi + gb);
            cpa16(sb + 3 * TILE_B + so, Blo + gb);
        }
        CP_COMMIT();
    }

    for (int kt = 0; kt < nk; kt++) {
        if (kt + 1 < nk) {
            uint32_t st = ((kt + 1) & 1) * 4 * TILE_B;
            int k0 = (kt + 1) << 5;
#pragma unroll
            for (int i = 0; i < 2; i++) {
                int q = tid + i * 256;
                int r = q >> 2, cc = (q & 3) << 3;
                uint32_t so = r * 80 + cc * 2;
                size_t ga = (size_t)(m0 + r) * lda + k0 + cc;
                size_t gb = (size_t)(n0 + r) * ldb + k0 + cc;
                cpa16(sb + st + 0 * TILE_B + so, Ahi + ga);
                cpa16(sb + st + 1 * TILE_B + so, Alo + ga);
                cpa16(sb + st + 2 * TILE_B + so, Bhi + gb);
                cpa16(sb + st + 3 * TILE_B + so, Blo + gb);
            }
            CP_COMMIT();
            CP_WAIT1();
        } else {
            CP_WAIT0();
        }
        __syncthreads();

        const uint32_t base = sb + (kt & 1) * 4 * TILE_B;
        const uint32_t uAh = base, uAl = base + TILE_B, uBh = base + 2 * TILE_B, uBl = base + 3 * TILE_B;
#pragma unroll
        for (int kk = 0; kk < 32; kk += 16) {
            uint32_t ah[2][4], al[2][4], bh[4][4], bl[4][4];
#pragma unroll
            for (int mt = 0; mt < 2; mt++) {
                uint32_t row = wm + mt * 16 + (lid & 15);
                uint32_t col = kk + ((lid & 16) >> 1);
                uint32_t off = row * 80 + col * 2;
                ldm_x4(ah[mt], uAh + off);
                ldm_x4(al[mt], uAl + off);
            }
#pragma unroll
            for (int p = 0; p < 4; p++) {
                uint32_t row = wn + p * 16 + (lid & 7) + ((lid & 16) >> 1);
                uint32_t col = kk + (lid & 8);
                uint32_t off = row * 80 + col * 2;
                ldm_x4(bh[p], uBh + off);
                ldm_x4(bl[p], uBl + off);
            }
#pragma unroll
            for (int mt = 0; mt < 2; mt++)
#pragma unroll
                for (int nt = 0; nt < 8; nt++) {
                    const uint32_t* bhp = &bh[nt >> 1][(nt & 1) << 1];
                    const uint32_t* blp = &bl[nt >> 1][(nt & 1) << 1];
                    mma16816(acc[mt][nt], ah[mt], bhp);
                    mma16816(acc[mt][nt], ah[mt], blp);
                    mma16816(acc[mt][nt], al[mt], bhp);
                }
        }
        __syncthreads();
    }

    // ---- epilogue ----
    const int g = lid >> 2, t2 = (lid & 3) << 1;
    float* scol = (float*)(smem + 8 * TILE_B);
    float csl[16];
    if (EPI == 2) {
        if (tid < 128) scol[tid] = 0.f;
#pragma unroll
        for (int i = 0; i < 16; i++) csl[i] = 0.f;
        __syncthreads();
    }
#pragma unroll
    for (int mt = 0; mt < 2; mt++) {
        int r0 = m0 + wm + mt * 16 + g;
#pragma unroll
        for (int nt = 0; nt < 8; nt++) {
            int col = n0 + wn + nt * 8 + t2;
            float* a = acc[mt][nt];
            float b0 = 0.f, b1 = 0.f;
            if (EPI < 2) { b0 = __ldg(&bias[col]); b1 = __ldg(&bias[col + 1]); }
#pragma unroll
            for (int hrow = 0; hrow < 2; hrow++) {
                int row = r0 + hrow * 8;
                float vx = a[hrow * 2 + 0], vy = a[hrow * 2 + 1];
                if (EPI == 2) {
                    vx = __expf(ALPHA_C * (vx + EPS_C));
                    vy = __expf(ALPHA_C * (vy + EPS_C));
                    csl[nt * 2 + 0] += vx;
                    csl[nt * 2 + 1] += vy;
                    *(float2*)&C[(size_t)row * ldc + col] = make_float2(vx, vy);
                } else {
                    vx += b0; vy += b1;
                    if (EPI == 0) { vx = fmaxf(vx, 0.f); vy = fmaxf(vy, 0.f); }
                    *(float2*)&C[(size_t)row * ldc + col] = make_float2(vx, vy);
                    if (EPI == 0) {
                        __nv_bfloat16 h0, l0, h1, l1;
                        split1(vx, h0, l0); split1(vy, h1, l1);
                        *(uint32_t*)&Chi[(size_t)row * ldc + col] = pack_bf2(h0, h1);
                        *(uint32_t*)&Clo[(size_t)row * ldc + col] = pack_bf2(l0, l1);
                    }
                }
            }
        }
    }
    if (EPI == 2) {
#pragma unroll
        for (int nt = 0; nt < 8; nt++) {
            atomicAdd(&scol[wn + nt * 8 + t2 + 0], csl[nt * 2 + 0]);
            atomicAdd(&scol[wn + nt * 8 + t2 + 1], csl[nt * 2 + 1]);
        }
        __syncthreads();
        if (tid < 128) atomicAdd(&cs0[n0 + tid], scol[tid]);
    }
}

// ---------------- l2 normalize + split to bf16 (gap rows zeroed) ----------------
__global__ void l2norm_split_kernel()
{
    int row = blockIdx.x, t = threadIdx.x;
    bool gap = (row >= NSRC && row < TOFF);
    float v = gap ? 0.f : g_feat[(size_t)row * 256 + t];
    float s = v * v;
#pragma unroll
    for (int o = 16; o; o >>= 1) s += __shfl_xor_sync(0xffffffffu, s, o);
    __shared__ float sm[8];
    int w = t >> 5;
    if ((t & 31) == 0) sm[w] = s;
    __syncthreads();
    if (t < 8) {
        float tot = sm[t];
#pragma unroll
        for (int o = 4; o; o >>= 1) tot += __shfl_xor_sync(0xffu, tot, o);
        if (t == 0) sm[0] = tot;
    }
    __syncthreads();
    float scale = 1.f / fmaxf(sqrtf(sm[0]), 1e-12f);
    float o = v * scale;
    __nv_bfloat16 h, l; split1(o, h, l);
    g_ft_hi[(size_t)row * 256 + t] = h;
    g_ft_lo[(size_t)row * 256 + t] = l;
}

// ---------------- fused sinkhorn row+col pass ----------------
// Block handles 8 rows. pass1: u_r = 1/sum_j S0[r][j]/cs[j]. pass2: csn[j] += sum_r u_r*S0[r][j].
__global__ __launch_bounds__(256, 1) void sink_rowcol_kernel(
    const float* __restrict__ cs, float* __restrict__ csn, const float* __restrict__ S0)
{
    int r0 = blockIdx.x * 8, t = threadIdx.x;
    float rv[16];
    float acc[8] = {};
#pragma unroll
    for (int c = 0; c < 4; c++) {
        int j = c * 1024 + t * 4;
        float4 cv = *(const float4*)&cs[j];
        rv[c * 4 + 0] = 1.f / cv.x; rv[c * 4 + 1] = 1.f / cv.y;
        rv[c * 4 + 2] = 1.f / cv.z; rv[c * 4 + 3] = 1.f / cv.w;
#pragma unroll
        for (int r = 0; r < 8; r++) {
            float4 s = *(const float4*)&S0[(size_t)(r0 + r) * NTGT + j];
            acc[r] += s.x * rv[c * 4] + s.y * rv[c * 4 + 1] + s.z * rv[c * 4 + 2] + s.w * rv[c * 4 + 3];
        }
    }
    __shared__ float red[8][8];
    __shared__ float su[8];
    int w = t >> 5, ln = t & 31;
#pragma unroll
    for (int r = 0; r < 8; r++) {
        float a = acc[r];
#pragma unroll
        for (int o = 16; o; o >>= 1) a += __shfl_xor_sync(0xffffffffu, a, o);
        if (ln == 0) red[w][r] = a;
    }
    __syncthreads();
    if (t < 8) {
        float s = 0.f;
#pragma unroll
        for (int w2 = 0; w2 < 8; w2++) s += red[w2][t];
        su[t] = 1.f / s;
    }
    __syncthreads();
    float u[8];
#pragma unroll
    for (int r = 0; r < 8; r++) u[r] = su[r];
#pragma unroll
    for (int c = 0; c < 4; c++) {
        int j = c * 1024 + t * 4;
        float4 ca = make_float4(0.f, 0.f, 0.f, 0.f);
#pragma unroll
        for (int r = 0; r < 8; r++) {
            float4 s = *(const float4*)&S0[(size_t)(r0 + r) * NTGT + j];
            ca.x += u[r] * s.x; ca.y += u[r] * s.y; ca.z += u[r] * s.z; ca.w += u[r] * s.w;
        }
        asm volatile("red.global.add.v4.f32 [%0], {%1,%2,%3,%4};"
                     :: "l"(&csn[j]), "f"(ca.x), "f"(ca.y), "f"(ca.z), "f"(ca.w) : "memory");
    }
}

// ---------------- final sinkhorn row pass + output write ----------------
__global__ __launch_bounds__(256, 1) void sink_rowout_kernel(
    const float* __restrict__ cs, float* __restrict__ out, const float* __restrict__ S0)
{
    int r0 = blockIdx.x * 8, t = threadIdx.x;
    float rv[16];
    float acc[8] = {};
#pragma unroll
    for (int c = 0; c < 4; c++) {
        int j = c * 1024 + t * 4;
        float4 cv = *(const float4*)&cs[j];
        rv[c * 4 + 0] = 1.f / cv.x; rv[c * 4 + 1] = 1.f / cv.y;
        rv[c * 4 + 2] = 1.f / cv.z; rv[c * 4 + 3] = 1.f / cv.w;
#pragma unroll
        for (int r = 0; r < 8; r++) {
            float4 s = *(const float4*)&S0[(size_t)(r0 + r) * NTGT + j];
            acc[r] += s.x * rv[c * 4] + s.y * rv[c * 4 + 1] + s.z * rv[c * 4 + 2] + s.w * rv[c * 4 + 3];
        }
    }
    __shared__ float red[8][8];
    __shared__ float su[8];
    int w = t >> 5, ln = t & 31;
#pragma unroll
    for (int r = 0; r < 8; r++) {
        float a = acc[r];
#pragma unroll
        for (int o = 16; o; o >>= 1) a += __shfl_xor_sync(0xffffffffu, a, o);
        if (ln == 0) red[w][r] = a;
    }
    __syncthreads();
    if (t < 8) {
        float s = 0.f;
#pragma unroll
        for (int w2 = 0; w2 < 8; w2++) s += red[w2][t];
        su[t] = 1.f / s;
    }
    __syncthreads();
    float u[8];
#pragma unroll
    for (int r = 0; r < 8; r++) u[r] = su[r];
#pragma unroll
    for (int c = 0; c < 4; c++) {
        int j = c * 1024 + t * 4;
#pragma unroll
        for (int r = 0; r < 8; r++) {
            float4 s = *(const float4*)&S0[(size_t)(r0 + r) * NTGT + j];
            float4 o;
            o.x = u[r] * s.x * rv[c * 4 + 0];
            o.y = u[r] * s.y * rv[c * 4 + 1];
            o.z = u[r] * s.z * rv[c * 4 + 2];
            o.w = u[r] * s.w * rv[c * 4 + 3];
            *(float4*)&out[(size_t)(r0 + r) * NTGT + j] = o;
        }
    }
}

// ---------------- host orchestration ----------------
extern "C" void kernel_launch(void* const* d_in, const int* in_sizes, int n_in,
                              void* d_out, int out_size)
{
    const float* x_s = (const float*)d_in[0];
    const float* x_t = (const float*)d_in[1];
    const int* edges = (const int*)d_in[2];
    const int* edget = (const int*)d_in[3];
    const float* W1_0 = (const float*)d_in[4];
    const float* W2_0 = (const float*)d_in[5];
    const float* Wr_0 = (const float*)d_in[6];
    const float* br_0 = (const float*)d_in[7];
    const float* W1_1 = (const float*)d_in[8];
    const float* W2_1 = (const float*)d_in[9];
    const float* Wr_1 = (const float*)d_in[10];
    const float* br_1 = (const float*)d_in[11];
    const float* W1_2 = (const float*)d_in[12];
    const float* W2_2 = (const float*)d_in[13];
    const float* Wr_2 = (const float*)d_in[14];
    const float* br_2 = (const float*)d_in[15];
    const float* final_w = (const float*)d_in[16];
    const float* final_b = (const float*)d_in[17];
    int ES = in_sizes[2] / 2;
    int ET = in_sizes[3] / 2;

    float *cat, *hcat, *feat, *S0, *cs;
    __nv_bfloat16 *cat_hi, *cat_lo, *hc_hi, *hc_lo, *ft_hi, *ft_lo, *wt_hi, *wt_lo;
    cudaGetSymbolAddress((void**)&cat, g_cat);
    cudaGetSymbolAddress((void**)&cat_hi, g_cat_hi);
    cudaGetSymbolAddress((void**)&cat_lo, g_cat_lo);
    cudaGetSymbolAddress((void**)&hcat, g_hcat);
    cudaGetSymbolAddress((void**)&hc_hi, g_hc_hi);
    cudaGetSymbolAddress((void**)&hc_lo, g_hc_lo);
    cudaGetSymbolAddress((void**)&feat, g_feat);
    cudaGetSymbolAddress((void**)&ft_hi, g_ft_hi);
    cudaGetSymbolAddress((void**)&ft_lo, g_ft_lo);
    cudaGetSymbolAddress((void**)&wt_hi, g_wt_hi);
    cudaGetSymbolAddress((void**)&wt_lo, g_wt_lo);
    cudaGetSymbolAddress((void**)&S0, g_S0);
    cudaGetSymbolAddress((void**)&cs, g_cs);

    cudaFuncSetAttribute(gemm_kernel<0>, cudaFuncAttributeMaxDynamicSharedMemorySize, SMEM_GEMM);
    cudaFuncSetAttribute(gemm_kernel<1>, cudaFuncAttributeMaxDynamicSharedMemorySize, SMEM_GEMM);
    cudaFuncSetAttribute(gemm_kernel<2>, cudaFuncAttributeMaxDynamicSharedMemorySize, SMEM_GEMM);

    // setup
    pack_wt_kernel<<<(720896 + 255) / 256, 256>>>(W1_0, W2_0, Wr_0, W1_1, W2_1, Wr_1,
                                                  W1_2, W2_2, Wr_2, final_w);
    init_kernel<<<NROW / 256, 256>>>();
    count_kernel<<<(ES + 255) / 256, 256>>>(edges, edges + ES, ES, 0);
    count_kernel<<<(ET + 255) / 256, 256>>>(edget, edget + ET, ET, TOFF);
    recip_kernel<<<NROW / 256, 256>>>();

    const float* brs[3] = {br_0, br_1, br_2};
    const int woff[3] = {0, 98304, 294912};

    for (int l = 0; l < 3; l++) {
        int fan = l ? 256 : 128;
        int fan3 = 3 * fan;
        if (l == 0) prep0_kernel<<<NROW * 96 / 256, 256>>>(x_s, x_t);
        else prep12_kernel<<<NROW * 192 / 256, 256>>>(cat + 128 + (l - 1) * 256);
        int shift = (fan == 128) ? 5 : 6;
        int st = (ES + ET) << shift;
        scatter_kernel<<<(st + 255) / 256, 256>>>(edges, edges + ES, ES,
                                                  edget, edget + ET, ET, shift, fan);
        int n4 = NROW * fan3 / 4;
        split_hcat_kernel<<<(n4 + 255) / 256, 256>>>(n4);
        gemm_kernel<0><<<dim3(NROW / 128, 2), 256, SMEM_GEMM>>>(
            hc_hi, hc_lo, fan3, wt_hi + woff[l], wt_lo + woff[l], fan3, fan3, brs[l],
            cat + 128 + l * 256, cat_hi + 128 + l * 256, cat_lo + 128 + l * 256, CATW, nullptr);
    }
    // final linear
    gemm_kernel<1><<<dim3(NROW / 128, 2), 256, SMEM_GEMM>>>(
        cat_hi, cat_lo, CATW, wt_hi + 491520, wt_lo + 491520, CATW, CATW, final_b,
        feat, nullptr, nullptr, 256, nullptr);
    l2norm_split_kernel<<<NROW, 256>>>();

    // match matrix: exp epilogue + fused first col-normalization sums into cs0
    gemm_kernel<2><<<dim3(NTGT / 128, NTGT / 128), 256, SMEM_GEMM>>>(
        ft_hi, ft_lo, 256, ft_hi + (size_t)TOFF * 256, ft_lo + (size_t)TOFF * 256, 256, 256,
        nullptr, S0, nullptr, nullptr, NTGT, cs);

    // sinkhorn: fused (row+col) x4, then row+out
    sink_rowcol_kernel<<<NTGT / 8, 256>>>(cs + 0 * NTGT, cs + 1 * NTGT, S0);
    sink_rowcol_kernel<<<NTGT / 8, 256>>>(cs + 1 * NTGT, cs + 2 * NTGT, S0);
    sink_rowcol_kernel<<<NTGT / 8, 256>>>(cs + 2 * NTGT, cs + 3 * NTGT, S0);
    sink_rowcol_kernel<<<NTGT / 8, 256>>>(cs + 3 * NTGT, cs + 4 * NTGT, S0);
    sink_rowout_kernel<<<NSRC / 8, 256>>>(cs + 4 * NTGT, (float*)d_out, S0);
}

// round 15
// speedup vs baseline: 1.8836x; 1.1124x over previous
#include <cuda_runtime.h>
#include <cuda_bf16.h>
#include <math.h>
#include <cstdint>

// Problem constants
#define NSRC 4000
#define NTGT 4096
#define TOFF 4096            // target tower row offset in merged node space
#define NROW 8192            // merged rows (4096 + 4096)
#define DIN 128
#define DH 256
#define CATW 896             // 128 + 3*256
#define ALPHA_C 20.0f
#define EPS_C 1e-10f
#define CAP 128              // per-node neighbor-list capacity (P(deg>128) ~ 1e-60)

// ================= generic-PTX helpers (sm_80+; NO tcgen05/arch-a) =================
__device__ __forceinline__ uint32_t smem_to_u32(const void* smem_ptr) {
    uint32_t addr;
    asm("{ .reg .u64 tmp; cvta.to.shared.u64 tmp, %1; cvt.u32.u64 %0, tmp; }"
        : "=r"(addr) : "l"(smem_ptr));
    return addr;
}
__device__ __forceinline__ void ldm_x4(uint32_t* r, uint32_t addr) {
    asm volatile("ldmatrix.sync.aligned.m8n8.x4.shared.b16 {%0,%1,%2,%3}, [%4];"
        : "=r"(r[0]), "=r"(r[1]), "=r"(r[2]), "=r"(r[3]) : "r"(addr));
}
__device__ __forceinline__ void mma16816(float* d, const uint32_t* a, const uint32_t* b) {
    asm volatile(
        "mma.sync.aligned.m16n8k16.row.col.f32.bf16.bf16.f32 "
        "{%0,%1,%2,%3}, {%4,%5,%6,%7}, {%8,%9}, {%0,%1,%2,%3};"
        : "+f"(d[0]), "+f"(d[1]), "+f"(d[2]), "+f"(d[3])
        : "r"(a[0]), "r"(a[1]), "r"(a[2]), "r"(a[3]), "r"(b[0]), "r"(b[1]));
}
__device__ __forceinline__ void cpa16(uint32_t saddr, const void* g) {
    asm volatile("cp.async.cg.shared.global [%0], [%1], 16;" :: "r"(saddr), "l"(g));
}
#define CP_COMMIT() asm volatile("cp.async.commit_group;" ::: "memory")
#define CP_WAIT1()  asm volatile("cp.async.wait_group 1;" ::: "memory")
#define CP_WAIT0()  asm volatile("cp.async.wait_group 0;" ::: "memory")
__device__ __forceinline__ uint32_t pack_bf2(__nv_bfloat16 a, __nv_bfloat16 b) {
    __nv_bfloat162 t = __halves2bfloat162(a, b);
    return *(uint32_t*)&t;
}
__device__ __forceinline__ void split1(float v, __nv_bfloat16& h, __nv_bfloat16& l) {
    h = __float2bfloat16(v);
    l = __float2bfloat16(v - __bfloat162float(h));
}

// ---------------- device scratch (static, no allocation) ----------------
__device__ __align__(128) float g_cat[(size_t)NROW * CATW];                 // fp32 concat features
__device__ __align__(128) __nv_bfloat16 g_cat_hi[(size_t)NROW * CATW];
__device__ __align__(128) __nv_bfloat16 g_cat_lo[(size_t)NROW * CATW];
__device__ __align__(128) __nv_bfloat16 g_hc_hi[(size_t)NROW * 768];
__device__ __align__(128) __nv_bfloat16 g_hc_lo[(size_t)NROW * 768];
__device__ __align__(128) float g_feat[(size_t)NROW * DH];
__device__ __align__(128) __nv_bfloat16 g_ft_hi[(size_t)NROW * DH];
__device__ __align__(128) __nv_bfloat16 g_ft_lo[(size_t)NROW * DH];
__device__ __align__(128) __nv_bfloat16 g_wt_hi[720896];                    // [256 x fan3] K-major
__device__ __align__(128) __nv_bfloat16 g_wt_lo[720896];
__device__ __align__(128) float g_S0[(size_t)NTGT * NTGT];                  // 64MB
__device__ __align__(128) float g_cs[5 * NTGT];                             // colsum buffers
__device__ __align__(128) float g_rcd[NROW];
__device__ __align__(128) float g_rcs[NROW];
__device__ __align__(128) int g_incnt[NROW];
__device__ __align__(128) int g_outcnt[NROW];
__device__ __align__(128) int g_inlist[(size_t)NROW * CAP];
__device__ __align__(128) int g_outlist[(size_t)NROW * CAP];

// ---------------- weight packing: transposed + split [256 x fan3] ----------------
__global__ void pack_wt_kernel(const float* __restrict__ W1_0, const float* __restrict__ W2_0, const float* __restrict__ Wr_0,
                               const float* __restrict__ W1_1, const float* __restrict__ W2_1, const float* __restrict__ Wr_1,
                               const float* __restrict__ W1_2, const float* __restrict__ W2_2, const float* __restrict__ Wr_2,
                               const float* __restrict__ final_w)
{
    int g = blockIdx.x * 256 + threadIdx.x;
    if (g >= 720896) return;
    float v;
    if (g < 98304) {
        int n = g / 384, k = g - n * 384;
        int sub = k >> 7, kr = k & 127;
        const float* s = (sub == 0) ? Wr_0 : ((sub == 1) ? W1_0 : W2_0);
        v = s[kr * 256 + n];
    } else if (g < 294912) {
        int g2 = g - 98304;
        int n = g2 / 768, k = g2 - n * 768;
        int sub = k >> 8, kr = k & 255;
        const float* s = (sub == 0) ? Wr_1 : ((sub == 1) ? W1_1 : W2_1);
        v = s[kr * 256 + n];
    } else if (g < 491520) {
        int g2 = g - 294912;
        int n = g2 / 768, k = g2 - n * 768;
        int sub = k >> 8, kr = k & 255;
        const float* s = (sub == 0) ? Wr_2 : ((sub == 1) ? W1_2 : W2_2);
        v = s[kr * 256 + n];
    } else {
        int g2 = g - 491520;
        int n = g2 / 896, k = g2 - n * 896;
        v = final_w[k * 256 + n];
    }
    __nv_bfloat16 h, l; split1(v, h, l);
    g_wt_hi[g] = h; g_wt_lo[g] = l;
}

// ---------------- init: zero degree counters + colsum buffers ----------------
__global__ void init_kernel()
{
    int i = blockIdx.x * 256 + threadIdx.x;
    if (i < NROW) { g_incnt[i] = 0; g_outcnt[i] = 0; }
    if (i < NTGT) {
#pragma unroll
        for (int b = 0; b < 5; b++) g_cs[b * NTGT + i] = 0.f;
    }
}

// ---------------- fill fixed-capacity adjacency lists ----------------
__global__ void fill_kernel(const int* __restrict__ es_s, const int* __restrict__ ed_s, int Es,
                            const int* __restrict__ es_t, const int* __restrict__ ed_t, int Et)
{
    int e = blockIdx.x * 256 + threadIdx.x;
    if (e >= Es + Et) return;
    int s, d;
    if (e < Es) { s = es_s[e]; d = ed_s[e]; }
    else { int e2 = e - Es; s = es_t[e2] + TOFF; d = ed_t[e2] + TOFF; }
    int sl = atomicAdd(&g_incnt[d], 1);
    if (sl < CAP) g_inlist[(size_t)d * CAP + sl] = s;
    int sl2 = atomicAdd(&g_outcnt[s], 1);
    if (sl2 < CAP) g_outlist[(size_t)s * CAP + sl2] = d;
}

__global__ void recip_kernel()
{
    int i = blockIdx.x * 256 + threadIdx.x;
    if (i < NROW) {
        g_rcd[i] = 1.f / fmaxf((float)g_incnt[i], 1.f);
        g_rcs[i] = 1.f / fmaxf((float)g_outcnt[i], 1.f);
    }
}

// ---------------- layer 0 gather: root=x, agg via lists, write hc hi/lo + cat hi/lo ----------------
__global__ __launch_bounds__(256, 1) void gather0_kernel(const float* __restrict__ xs, const float* __restrict__ xt)
{
    __shared__ int lists[2][2][CAP];
    __shared__ int cnts[2][2];
    int tid = threadIdx.x;
    int half = tid >> 7;
    int col = tid & 127;
    int node = blockIdx.x * 2 + half;
    if (col == 0) {
        cnts[half][0] = min(g_incnt[node], CAP);
        cnts[half][1] = min(g_outcnt[node], CAP);
    }
    __syncthreads();
    int ic = cnts[half][0], oc = cnts[half][1];
    if (col < ic) lists[half][0][col] = g_inlist[(size_t)node * CAP + col];
    if (col < oc) lists[half][1][col] = g_outlist[(size_t)node * CAP + col];
    __syncthreads();

    float root = 0.f;
    if (node < NSRC) root = xs[(size_t)node * 128 + col];
    else if (node >= TOFF) root = xt[(size_t)(node - TOFF) * 128 + col];

    float a1 = 0.f, a2 = 0.f;
#pragma unroll 4
    for (int i = 0; i < ic; i++) {
        int nb = lists[half][0][i];
        float hv = (nb < NSRC) ? xs[(size_t)nb * 128 + col]
                 : ((nb >= TOFF) ? xt[(size_t)(nb - TOFF) * 128 + col] : 0.f);
        a1 += hv;
    }
#pragma unroll 4
    for (int i = 0; i < oc; i++) {
        int nb = lists[half][1][i];
        float hv = (nb < NSRC) ? xs[(size_t)nb * 128 + col]
                 : ((nb >= TOFF) ? xt[(size_t)(nb - TOFF) * 128 + col] : 0.f);
        a2 += hv;
    }
    a1 *= g_rcd[node];
    a2 *= g_rcs[node];

    size_t o = (size_t)node * 384;
    __nv_bfloat16 h, l;
    split1(root, h, l);
    g_hc_hi[o + col] = h; g_hc_lo[o + col] = l;
    size_t oc2 = (size_t)node * CATW + col;
    g_cat[oc2] = root;
    g_cat_hi[oc2] = h; g_cat_lo[oc2] = l;
    split1(a1, h, l);
    g_hc_hi[o + 128 + col] = h; g_hc_lo[o + 128 + col] = l;
    split1(a2, h, l);
    g_hc_hi[o + 256 + col] = h; g_hc_lo[o + 256 + col] = l;
}

// ---------------- layers 1-2 gather: root = cat column block (fan=256) ----------------
__global__ __launch_bounds__(256, 1) void gather12_kernel(const float* __restrict__ h)
{
    __shared__ int lin[CAP], lout[CAP];
    __shared__ int sc[2];
    int col = threadIdx.x;
    int node = blockIdx.x;
    if (col == 0) {
        sc[0] = min(g_incnt[node], CAP);
        sc[1] = min(g_outcnt[node], CAP);
    }
    __syncthreads();
    int ic = sc[0], oc = sc[1];
    if (col < ic) lin[col] = g_inlist[(size_t)node * CAP + col];
    if (col < oc) lout[col] = g_outlist[(size_t)node * CAP + col];
    __syncthreads();

    float root = h[(size_t)node * CATW + col];
    float a1 = 0.f, a2 = 0.f;
#pragma unroll 4
    for (int i = 0; i < ic; i++) a1 += h[(size_t)lin[i] * CATW + col];
#pragma unroll 4
    for (int i = 0; i < oc; i++) a2 += h[(size_t)lout[i] * CATW + col];
    a1 *= g_rcd[node];
    a2 *= g_rcs[node];

    size_t o = (size_t)node * 768;
    __nv_bfloat16 hh, ll;
    split1(root, hh, ll);
    g_hc_hi[o + col] = hh; g_hc_lo[o + col] = ll;
    split1(a1, hh, ll);
    g_hc_hi[o + 256 + col] = hh; g_hc_lo[o + 256 + col] = ll;
    split1(a2, hh, ll);
    g_hc_hi[o + 512 + col] = hh; g_hc_lo[o + 512 + col] = ll;
}

// ================= HMMA bf16-split GEMM, cp.async 2-stage =================
// CTA = 128x128, 8 warps 4x2, warp 32x64. 3 passes Ah*Bh + Ah*Bl + Al*Bh.
// EPI: 0 = bias+relu, write C fp32 + Chi/Clo bf16 ; 1 = bias, C fp32 ; 2 = exp + colsum into cs0
#define PAD 40                      // bf16/row in smem (80B stride, conflict-free ldmatrix)
#define TILE_B 10240                // 128*PAD*2 bytes
#define SMEM_GEMM (2*4*TILE_B + 512)

template<int EPI>
__global__ __launch_bounds__(256, 1) void gemm_kernel(
    const __nv_bfloat16* __restrict__ Ahi, const __nv_bfloat16* __restrict__ Alo, int lda,
    const __nv_bfloat16* __restrict__ Bhi, const __nv_bfloat16* __restrict__ Blo, int ldb,
    int K, const float* __restrict__ bias,
    float* __restrict__ C, __nv_bfloat16* __restrict__ Chi, __nv_bfloat16* __restrict__ Clo,
    int ldc, float* __restrict__ cs0)
{
    extern __shared__ char smem[];
    const uint32_t sb = smem_to_u32(smem);
    const int tid = threadIdx.x, wid = tid >> 5, lid = tid & 31;
    const int m0 = blockIdx.x * 128, n0 = blockIdx.y * 128;
    const int wm = (wid >> 1) * 32, wn = (wid & 1) * 64;

    const int nk = K >> 5;
    float acc[2][8][4] = {};

    // prefetch stage 0
    {
#pragma unroll
        for (int i = 0; i < 2; i++) {
            int q = tid + i * 256;
            int r = q >> 2, cc = (q & 3) << 3;
            uint32_t so = r * 80 + cc * 2;
            size_t ga = (size_t)(m0 + r) * lda + cc;
            size_t gb = (size_t)(n0 + r) * ldb + cc;
            cpa16(sb + 0 * TILE_B + so, Ahi + ga);
            cpa16(sb + 1 * TILE_B + so, Alo + ga);
            cpa16(sb + 2 * TILE_B + so, Bhi + gb);
            cpa16(sb + 3 * TILE_B + so, Blo + gb);
        }
        CP_COMMIT();
    }

    for (int kt = 0; kt < nk; kt++) {
        if (kt + 1 < nk) {
            uint32_t st = ((kt + 1) & 1) * 4 * TILE_B;
            int k0 = (kt + 1) << 5;
#pragma unroll
            for (int i = 0; i < 2; i++) {
                int q = tid + i * 256;
                int r = q >> 2, cc = (q & 3) << 3;
                uint32_t so = r * 80 + cc * 2;
                size_t ga = (size_t)(m0 + r) * lda + k0 + cc;
                size_t gb = (size_t)(n0 + r) * ldb + k0 + cc;
                cpa16(sb + st + 0 * TILE_B + so, Ahi + ga);
                cpa16(sb + st + 1 * TILE_B + so, Alo + ga);
                cpa16(sb + st + 2 * TILE_B + so, Bhi + gb);
                cpa16(sb + st + 3 * TILE_B + so, Blo + gb);
            }
            CP_COMMIT();
            CP_WAIT1();
        } else {
            CP_WAIT0();
        }
        __syncthreads();

        const uint32_t base = sb + (kt & 1) * 4 * TILE_B;
        const uint32_t uAh = base, uAl = base + TILE_B, uBh = base + 2 * TILE_B, uBl = base + 3 * TILE_B;
#pragma unroll
        for (int kk = 0; kk < 32; kk += 16) {
            uint32_t ah[2][4], al[2][4], bh[4][4], bl[4][4];
#pragma unroll
            for (int mt = 0; mt < 2; mt++) {
                uint32_t row = wm + mt * 16 + (lid & 15);
                uint32_t col = kk + ((lid & 16) >> 1);
                uint32_t off = row * 80 + col * 2;
                ldm_x4(ah[mt], uAh + off);
                ldm_x4(al[mt], uAl + off);
            }
#pragma unroll
            for (int p = 0; p < 4; p++) {
                uint32_t row = wn + p * 16 + (lid & 7) + ((lid & 16) >> 1);
                uint32_t col = kk + (lid & 8);
                uint32_t off = row * 80 + col * 2;
                ldm_x4(bh[p], uBh + off);
                ldm_x4(bl[p], uBl + off);
            }
#pragma unroll
            for (int mt = 0; mt < 2; mt++)
#pragma unroll
                for (int nt = 0; nt < 8; nt++) {
                    const uint32_t* bhp = &bh[nt >> 1][(nt & 1) << 1];
                    const uint32_t* blp = &bl[nt >> 1][(nt & 1) << 1];
                    mma16816(acc[mt][nt], ah[mt], bhp);
                    mma16816(acc[mt][nt], ah[mt], blp);
                    mma16816(acc[mt][nt], al[mt], bhp);
                }
        }
        __syncthreads();
    }

    // ---- epilogue ----
    const int g = lid >> 2, t2 = (lid & 3) << 1;
    float* scol = (float*)(smem + 8 * TILE_B);
    float csl[16];
    if (EPI == 2) {
        if (tid < 128) scol[tid] = 0.f;
#pragma unroll
        for (int i = 0; i < 16; i++) csl[i] = 0.f;
        __syncthreads();
    }
#pragma unroll
    for (int mt = 0; mt < 2; mt++) {
        int r0 = m0 + wm + mt * 16 + g;
#pragma unroll
        for (int nt = 0; nt < 8; nt++) {
            int col = n0 + wn + nt * 8 + t2;
            float* a = acc[mt][nt];
            float b0 = 0.f, b1 = 0.f;
            if (EPI < 2) { b0 = __ldg(&bias[col]); b1 = __ldg(&bias[col + 1]); }
#pragma unroll
            for (int hrow = 0; hrow < 2; hrow++) {
                int row = r0 + hrow * 8;
                float vx = a[hrow * 2 + 0], vy = a[hrow * 2 + 1];
                if (EPI == 2) {
                    vx = __expf(ALPHA_C * (vx + EPS_C));
                    vy = __expf(ALPHA_C * (vy + EPS_C));
                    csl[nt * 2 + 0] += vx;
                    csl[nt * 2 + 1] += vy;
                    *(float2*)&C[(size_t)row * ldc + col] = make_float2(vx, vy);
                } else {
                    vx += b0; vy += b1;
                    if (EPI == 0) { vx = fmaxf(vx, 0.f); vy = fmaxf(vy, 0.f); }
                    *(float2*)&C[(size_t)row * ldc + col] = make_float2(vx, vy);
                    if (EPI == 0) {
                        __nv_bfloat16 h0, l0, h1, l1;
                        split1(vx, h0, l0); split1(vy, h1, l1);
                        *(uint32_t*)&Chi[(size_t)row * ldc + col] = pack_bf2(h0, h1);
                        *(uint32_t*)&Clo[(size_t)row * ldc + col] = pack_bf2(l0, l1);
                    }
                }
            }
        }
    }
    if (EPI == 2) {
#pragma unroll
        for (int nt = 0; nt < 8; nt++) {
            atomicAdd(&scol[wn + nt * 8 + t2 + 0], csl[nt * 2 + 0]);
            atomicAdd(&scol[wn + nt * 8 + t2 + 1], csl[nt * 2 + 1]);
        }
        __syncthreads();
        if (tid < 128) atomicAdd(&cs0[n0 + tid], scol[tid]);
    }
}

// ---------------- l2 normalize + split to bf16 (gap rows zeroed) ----------------
__global__ void l2norm_split_kernel()
{
    int row = blockIdx.x, t = threadIdx.x;
    bool gap = (row >= NSRC && row < TOFF);
    float v = gap ? 0.f : g_feat[(size_t)row * 256 + t];
    float s = v * v;
#pragma unroll
    for (int o = 16; o; o >>= 1) s += __shfl_xor_sync(0xffffffffu, s, o);
    __shared__ float sm[8];
    int w = t >> 5;
    if ((t & 31) == 0) sm[w] = s;
    __syncthreads();
    if (t < 8) {
        float tot = sm[t];
#pragma unroll
        for (int o = 4; o; o >>= 1) tot += __shfl_xor_sync(0xffu, tot, o);
        if (t == 0) sm[0] = tot;
    }
    __syncthreads();
    float scale = 1.f / fmaxf(sqrtf(sm[0]), 1e-12f);
    float o = v * scale;
    __nv_bfloat16 h, l; split1(o, h, l);
    g_ft_hi[(size_t)row * 256 + t] = h;
    g_ft_lo[(size_t)row * 256 + t] = l;
}

// ---------------- fused sinkhorn row+col pass ----------------
__global__ __launch_bounds__(256, 1) void sink_rowcol_kernel(
    const float* __restrict__ cs, float* __restrict__ csn, const float* __restrict__ S0)
{
    int r0 = blockIdx.x * 8, t = threadIdx.x;
    float rv[16];
    float acc[8] = {};
#pragma unroll
    for (int c = 0; c < 4; c++) {
        int j = c * 1024 + t * 4;
        float4 cv = *(const float4*)&cs[j];
        rv[c * 4 + 0] = 1.f / cv.x; rv[c * 4 + 1] = 1.f / cv.y;
        rv[c * 4 + 2] = 1.f / cv.z; rv[c * 4 + 3] = 1.f / cv.w;
#pragma unroll
        for (int r = 0; r < 8; r++) {
            float4 s = *(const float4*)&S0[(size_t)(r0 + r) * NTGT + j];
            acc[r] += s.x * rv[c * 4] + s.y * rv[c * 4 + 1] + s.z * rv[c * 4 + 2] + s.w * rv[c * 4 + 3];
        }
    }
    __shared__ float red[8][8];
    __shared__ float su[8];
    int w = t >> 5, ln = t & 31;
#pragma unroll
    for (int r = 0; r < 8; r++) {
        float a = acc[r];
#pragma unroll
        for (int o = 16; o; o >>= 1) a += __shfl_xor_sync(0xffffffffu, a, o);
        if (ln == 0) red[w][r] = a;
    }
    __syncthreads();
    if (t < 8) {
        float s = 0.f;
#pragma unroll
        for (int w2 = 0; w2 < 8; w2++) s += red[w2][t];
        su[t] = 1.f / s;
    }
    __syncthreads();
    float u[8];
#pragma unroll
    for (int r = 0; r < 8; r++) u[r] = su[r];
#pragma unroll
    for (int c = 0; c < 4; c++) {
        int j = c * 1024 + t * 4;
        float4 ca = make_float4(0.f, 0.f, 0.f, 0.f);
#pragma unroll
        for (int r = 0; r < 8; r++) {
            float4 s = *(const float4*)&S0[(size_t)(r0 + r) * NTGT + j];
            ca.x += u[r] * s.x; ca.y += u[r] * s.y; ca.z += u[r] * s.z; ca.w += u[r] * s.w;
        }
        asm volatile("red.global.add.v4.f32 [%0], {%1,%2,%3,%4};"
                     :: "l"(&csn[j]), "f"(ca.x), "f"(ca.y), "f"(ca.z), "f"(ca.w) : "memory");
    }
}

// ---------------- final sinkhorn row pass + output write ----------------
__global__ __launch_bounds__(256, 1) void sink_rowout_kernel(
    const float* __restrict__ cs, float* __restrict__ out, const float* __restrict__ S0)
{
    int r0 = blockIdx.x * 8, t = threadIdx.x;
    float rv[16];
    float acc[8] = {};
#pragma unroll
    for (int c = 0; c < 4; c++) {
        int j = c * 1024 + t * 4;
        float4 cv = *(const float4*)&cs[j];
        rv[c * 4 + 0] = 1.f / cv.x; rv[c * 4 + 1] = 1.f / cv.y;
        rv[c * 4 + 2] = 1.f / cv.z; rv[c * 4 + 3] = 1.f / cv.w;
#pragma unroll
        for (int r = 0; r < 8; r++) {
            float4 s = *(const float4*)&S0[(size_t)(r0 + r) * NTGT + j];
            acc[r] += s.x * rv[c * 4] + s.y * rv[c * 4 + 1] + s.z * rv[c * 4 + 2] + s.w * rv[c * 4 + 3];
        }
    }
    __shared__ float red[8][8];
    __shared__ float su[8];
    int w = t >> 5, ln = t & 31;
#pragma unroll
    for (int r = 0; r < 8; r++) {
        float a = acc[r];
#pragma unroll
        for (int o = 16; o; o >>= 1) a += __shfl_xor_sync(0xffffffffu, a, o);
        if (ln == 0) red[w][r] = a;
    }
    __syncthreads();
    if (t < 8) {
        float s = 0.f;
#pragma unroll
        for (int w2 = 0; w2 < 8; w2++) s += red[w2][t];
        su[t] = 1.f / s;
    }
    __syncthreads();
    float u[8];
#pragma unroll
    for (int r = 0; r < 8; r++) u[r] = su[r];
#pragma unroll
    for (int c = 0; c < 4; c++) {
        int j = c * 1024 + t * 4;
#pragma unroll
        for (int r = 0; r < 8; r++) {
            float4 s = *(const float4*)&S0[(size_t)(r0 + r) * NTGT + j];
            float4 o;
            o.x = u[r] * s.x * rv[c * 4 + 0];
            o.y = u[r] * s.y * rv[c * 4 + 1];
            o.z = u[r] * s.z * rv[c * 4 + 2];
            o.w = u[r] * s.w * rv[c * 4 + 3];
            *(float4*)&out[(size_t)(r0 + r) * NTGT + j] = o;
        }
    }
}

// ---------------- host orchestration ----------------
extern "C" void kernel_launch(void* const* d_in, const int* in_sizes, int n_in,
                              void* d_out, int out_size)
{
    const float* x_s = (const float*)d_in[0];
    const float* x_t = (const float*)d_in[1];
    const int* edges = (const int*)d_in[2];
    const int* edget = (const int*)d_in[3];
    const float* W1_0 = (const float*)d_in[4];
    const float* W2_0 = (const float*)d_in[5];
    const float* Wr_0 = (const float*)d_in[6];
    const float* br_0 = (const float*)d_in[7];
    const float* W1_1 = (const float*)d_in[8];
    const float* W2_1 = (const float*)d_in[9];
    const float* Wr_1 = (const float*)d_in[10];
    const float* br_1 = (const float*)d_in[11];
    const float* W1_2 = (const float*)d_in[12];
    const float* W2_2 = (const float*)d_in[13];
    const float* Wr_2 = (const float*)d_in[14];
    const float* br_2 = (const float*)d_in[15];
    const float* final_w = (const float*)d_in[16];
    const float* final_b = (const float*)d_in[17];
    int ES = in_sizes[2] / 2;
    int ET = in_sizes[3] / 2;

    float *cat, *feat, *S0, *cs;
    __nv_bfloat16 *cat_hi, *cat_lo, *hc_hi, *hc_lo, *ft_hi, *ft_lo, *wt_hi, *wt_lo;
    cudaGetSymbolAddress((void**)&cat, g_cat);
    cudaGetSymbolAddress((void**)&cat_hi, g_cat_hi);
    cudaGetSymbolAddress((void**)&cat_lo, g_cat_lo);
    cudaGetSymbolAddress((void**)&hc_hi, g_hc_hi);
    cudaGetSymbolAddress((void**)&hc_lo, g_hc_lo);
    cudaGetSymbolAddress((void**)&feat, g_feat);
    cudaGetSymbolAddress((void**)&ft_hi, g_ft_hi);
    cudaGetSymbolAddress((void**)&ft_lo, g_ft_lo);
    cudaGetSymbolAddress((void**)&wt_hi, g_wt_hi);
    cudaGetSymbolAddress((void**)&wt_lo, g_wt_lo);
    cudaGetSymbolAddress((void**)&S0, g_S0);
    cudaGetSymbolAddress((void**)&cs, g_cs);

    cudaFuncSetAttribute(gemm_kernel<0>, cudaFuncAttributeMaxDynamicSharedMemorySize, SMEM_GEMM);
    cudaFuncSetAttribute(gemm_kernel<1>, cudaFuncAttributeMaxDynamicSharedMemorySize, SMEM_GEMM);
    cudaFuncSetAttribute(gemm_kernel<2>, cudaFuncAttributeMaxDynamicSharedMemorySize, SMEM_GEMM);

    // setup: weights + adjacency lists
    pack_wt_kernel<<<(720896 + 255) / 256, 256>>>(W1_0, W2_0, Wr_0, W1_1, W2_1, Wr_1,
                                                  W1_2, W2_2, Wr_2, final_w);
    init_kernel<<<NROW / 256, 256>>>();
    fill_kernel<<<(ES + ET + 255) / 256, 256>>>(edges, edges + ES, ES, edget, edget + ET, ET);
    recip_kernel<<<NROW / 256, 256>>>();

    const float* brs[3] = {br_0, br_1, br_2};
    const int woff[3] = {0, 98304, 294912};

    for (int l = 0; l < 3; l++) {
        int fan = l ? 256 : 128;
        int fan3 = 3 * fan;
        if (l == 0) gather0_kernel<<<NROW / 2, 256>>>(x_s, x_t);
        else gather12_kernel<<<NROW, 256>>>(cat + 128 + (l - 1) * 256);
        gemm_kernel<0><<<dim3(NROW / 128, 2), 256, SMEM_GEMM>>>(
            hc_hi, hc_lo, fan3, wt_hi + woff[l], wt_lo + woff[l], fan3, fan3, brs[l],
            cat + 128 + l * 256, cat_hi + 128 + l * 256, cat_lo + 128 + l * 256, CATW, nullptr);
    }
    // final linear
    gemm_kernel<1><<<dim3(NROW / 128, 2), 256, SMEM_GEMM>>>(
        cat_hi, cat_lo, CATW, wt_hi + 491520, wt_lo + 491520, CATW, CATW, final_b,
        feat, nullptr, nullptr, 256, nullptr);
    l2norm_split_kernel<<<NROW, 256>>>();

    // match matrix: exp epilogue + fused first col-normalization sums into cs0
    gemm_kernel<2><<<dim3(NTGT / 128, NTGT / 128), 256, SMEM_GEMM>>>(
        ft_hi, ft_lo, 256, ft_hi + (size_t)TOFF * 256, ft_lo + (size_t)TOFF * 256, 256, 256,
        nullptr, S0, nullptr, nullptr, NTGT, cs);

    // sinkhorn: fused (row+col) x4, then row+out
    sink_rowcol_kernel<<<NTGT / 8, 256>>>(cs + 0 * NTGT, cs + 1 * NTGT, S0);
    sink_rowcol_kernel<<<NTGT / 8, 256>>>(cs + 1 * NTGT, cs + 2 * NTGT, S0);
    sink_rowcol_kernel<<<NTGT / 8, 256>>>(cs + 2 * NTGT, cs + 3 * NTGT, S0);
    sink_rowcol_kernel<<<NTGT / 8, 256>>>(cs + 3 * NTGT, cs + 4 * NTGT, S0);
    sink_rowout_kernel<<<NSRC / 8, 256>>>(cs + 4 * NTGT, (float*)d_out, S0);
}